// round 7
// baseline (speedup 1.0000x reference)
#include <cuda_runtime.h>
#include <cstdint>
#include <cstddef>

// Problem constants (fixed by setup_inputs)
#define BATCH 4
#define SEQ   1024
#define DIM   1152
#define HEADS 16
#define HDIM  72
#define ROWS  (BATCH*SEQ)          // 4096
#define QKVN  (3*DIM)              // 3456
#define TOTAL_ELEMS 4718592.0f     // B*H*N*hd for loss mean

// Scratch (static device allocation — allowed)
__device__ __align__(16) float g_qkv [(size_t)ROWS * QKVN];   // 56.6 MB
__device__ __align__(16) float g_xout[(size_t)ROWS * DIM];    // 18.9 MB

// ---------------------------------------------------------------------------
// GEMM: C[m,n] = sum_k A[m,k] * W[n,k] + bias[n]
// BM=128, BN=128, BK=16, 256 threads, 8x8 micro-tile, double-buffered smem.
// ---------------------------------------------------------------------------
__global__ __launch_bounds__(256)
void gemm_bias_kernel(const float* __restrict__ A, const float* __restrict__ W,
                      const float* __restrict__ bias, float* __restrict__ C,
                      int M, int N, int K)
{
    __shared__ __align__(16) float As[2][16][128];
    __shared__ __align__(16) float Bs[2][16][128];

    const int tid = threadIdx.x;
    const int tx = tid & 15;
    const int ty = tid >> 4;
    const int m0 = blockIdx.y * 128;
    const int n0 = blockIdx.x * 128;

    const int lrow = tid >> 2;
    const int lkc  = (tid & 3) << 2;

    const float* Ap0 = A + (size_t)(m0 + lrow) * K + lkc;
    const float* Ap1 = Ap0 + (size_t)64 * K;
    const float* Wp0 = W + (size_t)(n0 + lrow) * K + lkc;
    const float* Wp1 = Wp0 + (size_t)64 * K;

    float acc[8][8];
#pragma unroll
    for (int i = 0; i < 8; i++)
#pragma unroll
        for (int j = 0; j < 8; j++) acc[i][j] = 0.f;

    float4 pa0, pa1, pb0, pb1;

    pa0 = *(const float4*)Ap0;  pa1 = *(const float4*)Ap1;
    pb0 = *(const float4*)Wp0;  pb1 = *(const float4*)Wp1;
    {
        As[0][lkc+0][lrow] = pa0.x; As[0][lkc+1][lrow] = pa0.y;
        As[0][lkc+2][lrow] = pa0.z; As[0][lkc+3][lrow] = pa0.w;
        As[0][lkc+0][lrow+64] = pa1.x; As[0][lkc+1][lrow+64] = pa1.y;
        As[0][lkc+2][lrow+64] = pa1.z; As[0][lkc+3][lrow+64] = pa1.w;
        Bs[0][lkc+0][lrow] = pb0.x; Bs[0][lkc+1][lrow] = pb0.y;
        Bs[0][lkc+2][lrow] = pb0.z; Bs[0][lkc+3][lrow] = pb0.w;
        Bs[0][lkc+0][lrow+64] = pb1.x; Bs[0][lkc+1][lrow+64] = pb1.y;
        Bs[0][lkc+2][lrow+64] = pb1.z; Bs[0][lkc+3][lrow+64] = pb1.w;
    }
    __syncthreads();

    const int nkt = K >> 4;
    for (int kt = 0; kt < nkt; kt++) {
        const int buf = kt & 1;
        if (kt + 1 < nkt) {
            const int off = (kt + 1) << 4;
            pa0 = *(const float4*)(Ap0 + off);
            pa1 = *(const float4*)(Ap1 + off);
            pb0 = *(const float4*)(Wp0 + off);
            pb1 = *(const float4*)(Wp1 + off);
        }
#pragma unroll
        for (int k = 0; k < 16; k++) {
            float4 a0 = *(const float4*)&As[buf][k][ty * 8];
            float4 a1 = *(const float4*)&As[buf][k][ty * 8 + 4];
            float4 b0 = *(const float4*)&Bs[buf][k][tx * 8];
            float4 b1 = *(const float4*)&Bs[buf][k][tx * 8 + 4];
            float am[8] = {a0.x, a0.y, a0.z, a0.w, a1.x, a1.y, a1.z, a1.w};
            float bn[8] = {b0.x, b0.y, b0.z, b0.w, b1.x, b1.y, b1.z, b1.w};
#pragma unroll
            for (int i = 0; i < 8; i++)
#pragma unroll
                for (int j = 0; j < 8; j++) acc[i][j] += am[i] * bn[j];
        }
        if (kt + 1 < nkt) {
            const int nb = buf ^ 1;
            As[nb][lkc+0][lrow] = pa0.x; As[nb][lkc+1][lrow] = pa0.y;
            As[nb][lkc+2][lrow] = pa0.z; As[nb][lkc+3][lrow] = pa0.w;
            As[nb][lkc+0][lrow+64] = pa1.x; As[nb][lkc+1][lrow+64] = pa1.y;
            As[nb][lkc+2][lrow+64] = pa1.z; As[nb][lkc+3][lrow+64] = pa1.w;
            Bs[nb][lkc+0][lrow] = pb0.x; Bs[nb][lkc+1][lrow] = pb0.y;
            Bs[nb][lkc+2][lrow] = pb0.z; Bs[nb][lkc+3][lrow] = pb0.w;
            Bs[nb][lkc+0][lrow+64] = pb1.x; Bs[nb][lkc+1][lrow+64] = pb1.y;
            Bs[nb][lkc+2][lrow+64] = pb1.z; Bs[nb][lkc+3][lrow+64] = pb1.w;
        }
        __syncthreads();
    }

    const float4 bv0 = *(const float4*)&bias[n0 + tx * 8];
    const float4 bv1 = *(const float4*)&bias[n0 + tx * 8 + 4];
#pragma unroll
    for (int i = 0; i < 8; i++) {
        float* cp = C + (size_t)(m0 + ty * 8 + i) * N + n0 + tx * 8;
        float4 o0, o1;
        o0.x = acc[i][0] + bv0.x; o0.y = acc[i][1] + bv0.y;
        o0.z = acc[i][2] + bv0.z; o0.w = acc[i][3] + bv0.w;
        o1.x = acc[i][4] + bv1.x; o1.y = acc[i][5] + bv1.y;
        o1.z = acc[i][6] + bv1.z; o1.w = acc[i][7] + bv1.w;
        *(float4*)cp = o0;
        *(float4*)(cp + 4) = o1;
    }
}

// ---------------------------------------------------------------------------
// Attention v2: GEMM-style scores, padded V layout, register-prefetch pipeline.
// smem layout (floats):
//   Qs [72][64] swizzled-transposed   @ 0      (4608)
//   Ks [72][64] swizzled-transposed   @ 4608   (4608)
//   Vs [64][4][20] (18 dims + 2 pad)  @ 9216   (5120)
//   Ps [64][68]                       @ 14336  (4352)
//   smRow[64]                         @ 18688  (64)
// total 18752 floats = 75008 bytes (dynamic)
// ---------------------------------------------------------------------------
#define AT_SMEM_BYTES (18752 * 4)

__device__ __forceinline__ int qk_idx(int d, int k) {
    return d * 64 + ((((k >> 2) + 5 * d) & 15) << 2) + (k & 3);
}

__global__ __launch_bounds__(256)
void attn_kernel(const float* __restrict__ enc_k, const float* __restrict__ enc_v,
                 float* __restrict__ loss_out)
{
    extern __shared__ float sm[];
    float* Qs    = sm;
    float* Ks    = sm + 4608;
    float* Vs    = sm + 9216;
    float* Ps    = sm + 14336;
    float* smRow = sm + 18688;

    const int tid = threadIdx.x;
    const int bh = blockIdx.y, b = bh >> 4, h = bh & 15;
    const int n0 = blockIdx.x * 64;
    const float scale = rsqrtf((float)HDIM);

    // role layouts
    const int s_tx = tid & 15, s_ty = tid >> 4;   // score GEMM: 4q x 4k
    const int r_row = tid >> 2, r_sub = tid & 3;  // softmax
    const int p_q = tid >> 2, p_dg = tid & 3;     // PV: 1 query x 18 dims

    // ---- load Q tile once (scaled, swizzled transpose) ----
    {
        const float* qbase = g_qkv + ((size_t)(b * SEQ + n0)) * QKVN + h * HDIM;
#pragma unroll
        for (int r = 0; r < 9; r++) {
            int e = tid + r * 256;
            int q = e / 36, dpp = e - q * 36;
            int d = dpp * 2;
            float2 v = *(const float2*)(qbase + (size_t)q * QKVN + d);
            Qs[qk_idx(d,     q)] = v.x * scale;
            Qs[qk_idx(d + 1, q)] = v.y * scale;
        }
    }

    float xo[18];
    float lsum = 0.f;

    // prefetch registers (one tile ahead)
    float2 kp[9], vp[9];

    // prefetch pass 0, tile 0
    {
#pragma unroll
        for (int r = 0; r < 9; r++) {
            int e = tid + r * 256;
            int key = e / 36, dpp = e - key * 36, d = dpp * 2;
            const float* kb = g_qkv + ((size_t)(b * SEQ + key)) * QKVN + DIM + h * HDIM + d;
            kp[r] = *(const float2*)kb;
            vp[r] = *(const float2*)(kb + DIM);
        }
    }

    for (int pass = 0; pass < 2; pass++) {
        float m_ = -1e30f, l_ = 0.f;
        float O[18];
#pragma unroll
        for (int j = 0; j < 18; j++) O[j] = 0.f;

#pragma unroll 1
        for (int kt = 0; kt < 16; kt++) {
            __syncthreads();   // smem free from previous tile
            // ---- store prefetched K/V into smem ----
#pragma unroll
            for (int r = 0; r < 9; r++) {
                int e = tid + r * 256;
                int key = e / 36, dpp = e - key * 36, d = dpp * 2;
                Ks[qk_idx(d,     key)] = kp[r].x;
                Ks[qk_idx(d + 1, key)] = kp[r].y;
                int g = d / 18;
                *(float2*)&Vs[key * 80 + g * 20 + (d - g * 18)] = vp[r];
            }
            __syncthreads();

            // ---- prefetch next tile (overlaps with compute below) ----
            if (!(pass == 1 && kt == 15)) {
                const int npass = (kt == 15) ? 1 : pass;
                const int nkt   = (kt == 15) ? 0 : kt + 1;
                if (npass == 0) {
#pragma unroll
                    for (int r = 0; r < 9; r++) {
                        int e = tid + r * 256;
                        int key = e / 36, dpp = e - key * 36, d = dpp * 2;
                        const float* kb = g_qkv + ((size_t)(b * SEQ + nkt * 64 + key)) * QKVN
                                          + DIM + h * HDIM + d;
                        kp[r] = *(const float2*)kb;
                        vp[r] = *(const float2*)(kb + DIM);
                    }
                } else {
#pragma unroll
                    for (int r = 0; r < 9; r++) {
                        int e = tid + r * 256;
                        int key = e / 36, dpp = e - key * 36, d = dpp * 2;
                        size_t off = ((size_t)bh * SEQ + nkt * 64 + key) * HDIM + d;
                        kp[r] = *(const float2*)(enc_k + off);
                        vp[r] = *(const float2*)(enc_v + off);
                    }
                }
            }

            // ---- scores: S = Q K^T (4x4 per thread) ----
            {
                float s00=0,s01=0,s02=0,s03=0, s10=0,s11=0,s12=0,s13=0;
                float s20=0,s21=0,s22=0,s23=0, s30=0,s31=0,s32=0,s33=0;
#pragma unroll 8
                for (int d = 0; d < 72; d++) {
                    float4 qv = *(const float4*)&Qs[d * 64 + (((s_ty + 5 * d) & 15) << 2)];
                    float4 kv = *(const float4*)&Ks[d * 64 + (((s_tx + 5 * d) & 15) << 2)];
                    s00 += qv.x*kv.x; s01 += qv.x*kv.y; s02 += qv.x*kv.z; s03 += qv.x*kv.w;
                    s10 += qv.y*kv.x; s11 += qv.y*kv.y; s12 += qv.y*kv.z; s13 += qv.y*kv.w;
                    s20 += qv.z*kv.x; s21 += qv.z*kv.y; s22 += qv.z*kv.z; s23 += qv.z*kv.w;
                    s30 += qv.w*kv.x; s31 += qv.w*kv.y; s32 += qv.w*kv.z; s33 += qv.w*kv.w;
                }
                float* pr = Ps + (s_ty * 4) * 68 + s_tx * 4;
                pr[0]=s00; pr[1]=s01; pr[2]=s02; pr[3]=s03;  pr+=68;
                pr[0]=s10; pr[1]=s11; pr[2]=s12; pr[3]=s13;  pr+=68;
                pr[0]=s20; pr[1]=s21; pr[2]=s22; pr[3]=s23;  pr+=68;
                pr[0]=s30; pr[1]=s31; pr[2]=s32; pr[3]=s33;
            }
            __syncthreads();

            // ---- softmax: row r_row, cols r_sub*16..+15 ----
            {
                float* prow = Ps + r_row * 68 + r_sub * 16;
                float4 t0 = *(const float4*)(prow + 0);
                float4 t1 = *(const float4*)(prow + 4);
                float4 t2 = *(const float4*)(prow + 8);
                float4 t3 = *(const float4*)(prow + 12);
                float tmax = fmaxf(fmaxf(fmaxf(t0.x,t0.y),fmaxf(t0.z,t0.w)),
                                   fmaxf(fmaxf(t1.x,t1.y),fmaxf(t1.z,t1.w)));
                tmax = fmaxf(tmax, fmaxf(fmaxf(t2.x,t2.y),fmaxf(t2.z,t2.w)));
                tmax = fmaxf(tmax, fmaxf(fmaxf(t3.x,t3.y),fmaxf(t3.z,t3.w)));
                tmax = fmaxf(tmax, __shfl_xor_sync(0xffffffffu, tmax, 1));
                tmax = fmaxf(tmax, __shfl_xor_sync(0xffffffffu, tmax, 2));
                float nm = fmaxf(m_, tmax);
                float corr = __expf(m_ - nm);
                t0.x=__expf(t0.x-nm); t0.y=__expf(t0.y-nm); t0.z=__expf(t0.z-nm); t0.w=__expf(t0.w-nm);
                t1.x=__expf(t1.x-nm); t1.y=__expf(t1.y-nm); t1.z=__expf(t1.z-nm); t1.w=__expf(t1.w-nm);
                t2.x=__expf(t2.x-nm); t2.y=__expf(t2.y-nm); t2.z=__expf(t2.z-nm); t2.w=__expf(t2.w-nm);
                t3.x=__expf(t3.x-nm); t3.y=__expf(t3.y-nm); t3.z=__expf(t3.z-nm); t3.w=__expf(t3.w-nm);
                float ps = (t0.x+t0.y+t0.z+t0.w) + (t1.x+t1.y+t1.z+t1.w)
                         + (t2.x+t2.y+t2.z+t2.w) + (t3.x+t3.y+t3.z+t3.w);
                ps += __shfl_xor_sync(0xffffffffu, ps, 1);
                ps += __shfl_xor_sync(0xffffffffu, ps, 2);
                l_ = l_ * corr + ps;
                m_ = nm;
                *(float4*)(prow + 0)  = t0;
                *(float4*)(prow + 4)  = t1;
                *(float4*)(prow + 8)  = t2;
                *(float4*)(prow + 12) = t3;
                if (r_sub == 0) smRow[r_row] = corr;
            }
            __syncthreads();

            // ---- PV: O += P @ V (1 query x 18 dims per thread) ----
            {
                const float c0 = smRow[p_q];
#pragma unroll
                for (int j = 0; j < 18; j++) O[j] *= c0;
                const float* Pr = Ps + p_q * 68;
                const float* Vb = Vs + p_dg * 20;
#pragma unroll 2
                for (int k = 0; k < 64; k += 4) {
                    float4 pv = *(const float4*)(Pr + k);
                    float p4[4] = {pv.x, pv.y, pv.z, pv.w};
#pragma unroll
                    for (int u = 0; u < 4; u++) {
                        const float pw = p4[u];
                        const float* vr = Vb + (k + u) * 80;
                        float4 v0 = *(const float4*)vr;
                        float4 v1 = *(const float4*)(vr + 4);
                        float4 v2 = *(const float4*)(vr + 8);
                        float4 v3 = *(const float4*)(vr + 12);
                        float2 v4 = *(const float2*)(vr + 16);
                        O[0]  += pw*v0.x; O[1]  += pw*v0.y; O[2]  += pw*v0.z; O[3]  += pw*v0.w;
                        O[4]  += pw*v1.x; O[5]  += pw*v1.y; O[6]  += pw*v1.z; O[7]  += pw*v1.w;
                        O[8]  += pw*v2.x; O[9]  += pw*v2.y; O[10] += pw*v2.z; O[11] += pw*v2.w;
                        O[12] += pw*v3.x; O[13] += pw*v3.y; O[14] += pw*v3.z; O[15] += pw*v3.w;
                        O[16] += pw*v4.x; O[17] += pw*v4.y;
                    }
                }
            }
        }

        // ---- pass epilogue ----
        __syncthreads();
        if (r_sub == 0) smRow[r_row] = 1.0f / l_;
        __syncthreads();
        const float inv = smRow[p_q];
        if (pass == 0) {
            float* dst = g_xout + ((size_t)(b * SEQ + n0 + p_q)) * DIM + h * HDIM + p_dg * 18;
#pragma unroll
            for (int j = 0; j < 9; j++) {
                xo[2*j]   = O[2*j]   * inv;
                xo[2*j+1] = O[2*j+1] * inv;
                ((float2*)dst)[j] = make_float2(xo[2*j], xo[2*j+1]);
            }
        } else {
#pragma unroll
            for (int j = 0; j < 18; j++) {
                float e = xo[j] - O[j] * inv;
                lsum += e * e;
            }
        }
    }

    // loss reduction: warp reduce + one atomic per warp
    lsum *= (1.0f / TOTAL_ELEMS);
#pragma unroll
    for (int o = 16; o > 0; o >>= 1)
        lsum += __shfl_down_sync(0xffffffffu, lsum, o);
    if ((tid & 31) == 0) atomicAdd(loss_out, lsum);
}

// ---------------------------------------------------------------------------
extern "C" void kernel_launch(void* const* d_in, const int* in_sizes, int n_in,
                              void* d_out, int out_size)
{
    const float* x      = (const float*)d_in[0];
    const float* enc_k  = (const float*)d_in[1];
    const float* enc_v  = (const float*)d_in[2];
    const float* qkv_w  = (const float*)d_in[3];
    const float* qkv_b  = (const float*)d_in[4];
    const float* proj_w = (const float*)d_in[5];
    const float* proj_b = (const float*)d_in[6];
    float* out = (float*)d_out;
    float* loss_ptr = out + (out_size - 1);

    float* qkv_ptr = nullptr;
    float* xout_ptr = nullptr;
    cudaGetSymbolAddress((void**)&qkv_ptr,  g_qkv);
    cudaGetSymbolAddress((void**)&xout_ptr, g_xout);

    static bool attr_set = false;
    if (!attr_set) {
        cudaFuncSetAttribute(attn_kernel,
                             cudaFuncAttributeMaxDynamicSharedMemorySize,
                             AT_SMEM_BYTES);
        attr_set = true;
    }

    cudaMemsetAsync(loss_ptr, 0, sizeof(float));

    // 1) QKV GEMM: (4096,1152) @ (3456,1152)^T + b -> g_qkv
    gemm_bias_kernel<<<dim3(QKVN / 128, ROWS / 128), 256>>>(
        x, qkv_w, qkv_b, qkv_ptr, ROWS, QKVN, DIM);

    // 2) Dual attention + loss -> g_xout, loss scalar
    attn_kernel<<<dim3(SEQ / 64, BATCH * HEADS), 256, AT_SMEM_BYTES>>>(
        enc_k, enc_v, loss_ptr);

    // 3) Proj GEMM: (4096,1152) @ (1152,1152)^T + b -> out
    gemm_bias_kernel<<<dim3(DIM / 128, ROWS / 128), 256>>>(
        xout_ptr, proj_w, proj_b, out, ROWS, DIM, DIM);
}

// round 8
// speedup vs baseline: 1.5241x; 1.5241x over previous
#include <cuda_runtime.h>
#include <cuda_bf16.h>
#include <cstdint>
#include <cstddef>

// Problem constants (fixed by setup_inputs)
#define BATCH 4
#define SEQ   1024
#define DIM   1152
#define HEADS 16
#define HDIM  72
#define ROWS  (BATCH*SEQ)          // 4096
#define QKVN  (3*DIM)              // 3456
#define TOTAL_ELEMS 4718592.0f     // B*H*N*hd for loss mean

// Scratch (static device allocation — allowed)
__device__ __align__(16) float g_qkv [(size_t)ROWS * QKVN];   // 56.6 MB
__device__ __align__(16) float g_xout[(size_t)ROWS * DIM];    // 18.9 MB
// bf16 hi/lo split buffers
__device__ __align__(16) __nv_bfloat16 g_xh [(size_t)ROWS * DIM];
__device__ __align__(16) __nv_bfloat16 g_xl [(size_t)ROWS * DIM];
__device__ __align__(16) __nv_bfloat16 g_wqh[(size_t)QKVN * DIM];
__device__ __align__(16) __nv_bfloat16 g_wql[(size_t)QKVN * DIM];
__device__ __align__(16) __nv_bfloat16 g_wph[(size_t)DIM * DIM];
__device__ __align__(16) __nv_bfloat16 g_wpl[(size_t)DIM * DIM];
__device__ __align__(16) __nv_bfloat16 g_oh [(size_t)ROWS * DIM];
__device__ __align__(16) __nv_bfloat16 g_ol [(size_t)ROWS * DIM];

// ---------------------------------------------------------------------------
// fp32 -> bf16 (hi, lo) split: v = hi + lo + O(2^-18 v)
// ---------------------------------------------------------------------------
__global__ __launch_bounds__(256)
void split_bf16_kernel(const float* __restrict__ src,
                       __nv_bfloat16* __restrict__ hi,
                       __nv_bfloat16* __restrict__ lo, int n4)
{
    int i = blockIdx.x * 256 + threadIdx.x;
    if (i >= n4) return;
    float4 v = ((const float4*)src)[i];
    __nv_bfloat16 h0 = __float2bfloat16(v.x);
    __nv_bfloat16 h1 = __float2bfloat16(v.y);
    __nv_bfloat16 h2 = __float2bfloat16(v.z);
    __nv_bfloat16 h3 = __float2bfloat16(v.w);
    __nv_bfloat16 l0 = __float2bfloat16(v.x - __bfloat162float(h0));
    __nv_bfloat16 l1 = __float2bfloat16(v.y - __bfloat162float(h1));
    __nv_bfloat16 l2 = __float2bfloat16(v.z - __bfloat162float(h2));
    __nv_bfloat16 l3 = __float2bfloat16(v.w - __bfloat162float(h3));
    __nv_bfloat162 ph0; ph0.x = h0; ph0.y = h1;
    __nv_bfloat162 ph1; ph1.x = h2; ph1.y = h3;
    __nv_bfloat162 pl0; pl0.x = l0; pl0.y = l1;
    __nv_bfloat162 pl1; pl1.x = l2; pl1.y = l3;
    ((__nv_bfloat162*)hi)[2 * i]     = ph0;
    ((__nv_bfloat162*)hi)[2 * i + 1] = ph1;
    ((__nv_bfloat162*)lo)[2 * i]     = pl0;
    ((__nv_bfloat162*)lo)[2 * i + 1] = pl1;
}

// ---------------------------------------------------------------------------
// Tensor-core GEMM (3-term bf16 split): C[m,n] = sum_k A[m,k]*W[n,k] + bias[n]
// BM=128, BN=128, BK=32, 256 threads (8 warps as 2m x 4n, each 64x32).
// mma.sync.m16n8k16 row.col f32.bf16.bf16.f32; D += Ah*Bh + Ah*Bl + Al*Bh.
// smem: per stage 4 arrays [128][40] bf16 (80B row stride -> conflict-free
// 4B fragment loads). 2 stages = 81920 B dynamic smem, cp.async pipelined.
// ---------------------------------------------------------------------------
#define GM_SMEM_BYTES 81920

__device__ __forceinline__ void cp16(uint32_t dst, const void* src) {
    asm volatile("cp.async.cg.shared.global [%0], [%1], 16;" :: "r"(dst), "l"(src));
}
__device__ __forceinline__ void mma_bf16(float* d, const uint32_t* a, const uint32_t* b) {
    asm volatile(
        "mma.sync.aligned.m16n8k16.row.col.f32.bf16.bf16.f32 "
        "{%0,%1,%2,%3}, {%4,%5,%6,%7}, {%8,%9}, {%0,%1,%2,%3};"
        : "+f"(d[0]), "+f"(d[1]), "+f"(d[2]), "+f"(d[3])
        : "r"(a[0]), "r"(a[1]), "r"(a[2]), "r"(a[3]), "r"(b[0]), "r"(b[1]));
}

extern __shared__ char dynsm[];

__global__ __launch_bounds__(256)
void gemm_mma_kernel(const __nv_bfloat16* __restrict__ Ah, const __nv_bfloat16* __restrict__ Al,
                     const __nv_bfloat16* __restrict__ Bh, const __nv_bfloat16* __restrict__ Bl,
                     const float* __restrict__ bias, float* __restrict__ C,
                     int M, int N, int K)
{
    __nv_bfloat16* sb = (__nv_bfloat16*)dynsm;
    const uint32_t sb32 = (uint32_t)__cvta_generic_to_shared(sb);

    const int tid  = threadIdx.x;
    const int warp = tid >> 5, lane = tid & 31;
    const int wm = warp >> 2, wn = warp & 3;     // 2 x 4 warp grid
    const int gr = lane >> 2, c4 = lane & 3;     // fragment row / col groups
    const int m0 = blockIdx.y * 128, n0 = blockIdx.x * 128;

    // cp.async load coords (per-thread, 2 chunks per array)
    const int l_row0 = tid >> 2,            l_cb0 = (tid & 3) << 3;
    const int l_row1 = (tid + 256) >> 2,    l_cb1 = ((tid + 256) & 3) << 3;

    float acc[4][4][4];
#pragma unroll
    for (int i = 0; i < 4; i++)
#pragma unroll
        for (int j = 0; j < 4; j++)
#pragma unroll
            for (int r = 0; r < 4; r++) acc[i][j][r] = 0.f;

    const int nkt = K >> 5;   // 36

    // ---- tile loader ----
    auto load_tile = [&](int stage, int kt) {
        const int k0 = kt << 5;
        const uint32_t st = sb32 + stage * 40960u;
        // array smem byte offsets: Ah 0, Al 10240, Bh 20480, Bl 30720
        cp16(st + (uint32_t)(l_row0 * 80 + l_cb0 * 2),
             Ah + (size_t)(m0 + l_row0) * K + k0 + l_cb0);
        cp16(st + (uint32_t)(l_row1 * 80 + l_cb1 * 2),
             Ah + (size_t)(m0 + l_row1) * K + k0 + l_cb1);
        cp16(st + 10240u + (uint32_t)(l_row0 * 80 + l_cb0 * 2),
             Al + (size_t)(m0 + l_row0) * K + k0 + l_cb0);
        cp16(st + 10240u + (uint32_t)(l_row1 * 80 + l_cb1 * 2),
             Al + (size_t)(m0 + l_row1) * K + k0 + l_cb1);
        cp16(st + 20480u + (uint32_t)(l_row0 * 80 + l_cb0 * 2),
             Bh + (size_t)(n0 + l_row0) * K + k0 + l_cb0);
        cp16(st + 20480u + (uint32_t)(l_row1 * 80 + l_cb1 * 2),
             Bh + (size_t)(n0 + l_row1) * K + k0 + l_cb1);
        cp16(st + 30720u + (uint32_t)(l_row0 * 80 + l_cb0 * 2),
             Bl + (size_t)(n0 + l_row0) * K + k0 + l_cb0);
        cp16(st + 30720u + (uint32_t)(l_row1 * 80 + l_cb1 * 2),
             Bl + (size_t)(n0 + l_row1) * K + k0 + l_cb1);
        asm volatile("cp.async.commit_group;");
    };

    load_tile(0, 0);
    load_tile(1, 1);

    for (int kt = 0; kt < nkt; kt++) {
        if (kt + 1 < nkt) asm volatile("cp.async.wait_group 1;");
        else              asm volatile("cp.async.wait_group 0;");
        __syncthreads();

        const __nv_bfloat16* sAh = sb + (kt & 1) * 20480;
        const __nv_bfloat16* sAl = sAh + 5120;
        const __nv_bfloat16* sBh = sAh + 10240;
        const __nv_bfloat16* sBl = sAh + 15360;

#pragma unroll
        for (int ks = 0; ks < 2; ks++) {
            const int kb = ks * 16 + 2 * c4;
            uint32_t bh[4][2], bl[4][2];
#pragma unroll
            for (int j = 0; j < 4; j++) {
                const int nrow = wn * 32 + j * 8 + gr;
                const __nv_bfloat16* p = sBh + nrow * 40 + kb;
                const __nv_bfloat16* q = sBl + nrow * 40 + kb;
                bh[j][0] = *(const uint32_t*)p;
                bh[j][1] = *(const uint32_t*)(p + 8);
                bl[j][0] = *(const uint32_t*)q;
                bl[j][1] = *(const uint32_t*)(q + 8);
            }
#pragma unroll
            for (int i = 0; i < 4; i++) {
                const int ar = wm * 64 + i * 16 + gr;
                const __nv_bfloat16* p = sAh + ar * 40 + kb;
                const __nv_bfloat16* q = sAl + ar * 40 + kb;
                uint32_t ah[4], al[4];
                ah[0] = *(const uint32_t*)p;
                ah[1] = *(const uint32_t*)(p + 320);       // row +8
                ah[2] = *(const uint32_t*)(p + 8);         // k   +8
                ah[3] = *(const uint32_t*)(p + 328);
                al[0] = *(const uint32_t*)q;
                al[1] = *(const uint32_t*)(q + 320);
                al[2] = *(const uint32_t*)(q + 8);
                al[3] = *(const uint32_t*)(q + 328);
#pragma unroll
                for (int j = 0; j < 4; j++) {
                    mma_bf16(acc[i][j], ah, bh[j]);
                    mma_bf16(acc[i][j], ah, bl[j]);
                    mma_bf16(acc[i][j], al, bh[j]);
                }
            }
        }
        __syncthreads();
        if (kt + 2 < nkt) load_tile(kt & 1, kt + 2);
    }

    // ---- epilogue: bias + store fp32 ----
#pragma unroll
    for (int j = 0; j < 4; j++) {
        const int gn = n0 + wn * 32 + j * 8 + 2 * c4;
        const float b0 = bias[gn], b1 = bias[gn + 1];
#pragma unroll
        for (int i = 0; i < 4; i++) {
            const int gm = m0 + wm * 64 + i * 16 + gr;
            float2 w0, w1;
            w0.x = acc[i][j][0] + b0; w0.y = acc[i][j][1] + b1;
            w1.x = acc[i][j][2] + b0; w1.y = acc[i][j][3] + b1;
            *(float2*)&C[(size_t)gm * N + gn] = w0;
            *(float2*)&C[(size_t)(gm + 8) * N + gn] = w1;
        }
    }
}

// ---------------------------------------------------------------------------
// Attention (R5, known-good): GEMM-style scores, 2q x 9d PV, no prefetch.
// smem (floats): Qs[72][64]sw @0, Ks @4608, Vs[64][8][12] @9216,
//                Ps[64][68] @15360, smRow[64] @19712 -> 79104 bytes
// ---------------------------------------------------------------------------
#define AT_SMEM_BYTES (19776 * 4)

__device__ __forceinline__ int qk_idx(int d, int k) {
    return d * 64 + ((((k >> 2) + 5 * d) & 15) << 2) + (k & 3);
}
__device__ __forceinline__ int v_idx(int k, int d) {
    int s = d / 9;
    return k * 96 + s * 12 + (d - s * 9);
}

__global__ __launch_bounds__(256)
void attn_kernel(const float* __restrict__ enc_k, const float* __restrict__ enc_v,
                 float* __restrict__ loss_out)
{
    float* sm    = (float*)dynsm;
    float* Qs    = sm;
    float* Ks    = sm + 4608;
    float* Vs    = sm + 9216;
    float* Ps    = sm + 15360;
    float* smRow = sm + 19712;

    const int tid = threadIdx.x;
    const int bh = blockIdx.y, b = bh >> 4, h = bh & 15;
    const int n0 = blockIdx.x * 64;
    const float scale = rsqrtf((float)HDIM);

    const int s_tx = tid & 15, s_ty = tid >> 4;   // score GEMM: 4q x 4k
    const int r_row = tid >> 2, r_sub = tid & 3;  // softmax
    const int p_q = tid >> 3, p_dg = tid & 7;     // PV: 2q x 9d

    {
        const float* qbase = g_qkv + ((size_t)(b * SEQ + n0)) * QKVN + h * HDIM;
#pragma unroll
        for (int r = 0; r < 9; r++) {
            int e = tid + r * 256;
            int q = e / 36, dpp = e - q * 36;
            int d = dpp * 2;
            float2 v = *(const float2*)(qbase + (size_t)q * QKVN + d);
            Qs[qk_idx(d,     q)] = v.x * scale;
            Qs[qk_idx(d + 1, q)] = v.y * scale;
        }
    }

    float xo[18];
    float lsum = 0.f;

    for (int pass = 0; pass < 2; pass++) {
        float m_ = -1e30f, l_ = 0.f;
        float O[18];
#pragma unroll
        for (int j = 0; j < 18; j++) O[j] = 0.f;

#pragma unroll 1
        for (int kt = 0; kt < 16; kt++) {
            __syncthreads();
            if (pass == 0) {
                const float* kb = g_qkv + ((size_t)(b * SEQ + kt * 64)) * QKVN + DIM + h * HDIM;
                const float* vb = kb + DIM;
#pragma unroll
                for (int r = 0; r < 9; r++) {
                    int e = tid + r * 256;
                    int key = e / 36, dpp = e - key * 36;
                    int d = dpp * 2;
                    float2 kv = *(const float2*)(kb + (size_t)key * QKVN + d);
                    float2 vv = *(const float2*)(vb + (size_t)key * QKVN + d);
                    Ks[qk_idx(d,     key)] = kv.x;
                    Ks[qk_idx(d + 1, key)] = kv.y;
                    Vs[v_idx(key, d)]     = vv.x;
                    Vs[v_idx(key, d + 1)] = vv.y;
                }
            } else {
                const float* kb = enc_k + ((size_t)bh * SEQ + kt * 64) * HDIM;
                const float* vb = enc_v + ((size_t)bh * SEQ + kt * 64) * HDIM;
#pragma unroll
                for (int r = 0; r < 9; r++) {
                    int e = tid + r * 256;
                    int key = e / 36, dpp = e - key * 36;
                    int d = dpp * 2;
                    float2 kv = *(const float2*)(kb + (size_t)key * HDIM + d);
                    float2 vv = *(const float2*)(vb + (size_t)key * HDIM + d);
                    Ks[qk_idx(d,     key)] = kv.x;
                    Ks[qk_idx(d + 1, key)] = kv.y;
                    Vs[v_idx(key, d)]     = vv.x;
                    Vs[v_idx(key, d + 1)] = vv.y;
                }
            }
            __syncthreads();

            {
                float s00=0,s01=0,s02=0,s03=0, s10=0,s11=0,s12=0,s13=0;
                float s20=0,s21=0,s22=0,s23=0, s30=0,s31=0,s32=0,s33=0;
#pragma unroll 8
                for (int d = 0; d < 72; d++) {
                    float4 qv = *(const float4*)&Qs[d * 64 + (((s_ty + 5 * d) & 15) << 2)];
                    float4 kv = *(const float4*)&Ks[d * 64 + (((s_tx + 5 * d) & 15) << 2)];
                    s00 += qv.x*kv.x; s01 += qv.x*kv.y; s02 += qv.x*kv.z; s03 += qv.x*kv.w;
                    s10 += qv.y*kv.x; s11 += qv.y*kv.y; s12 += qv.y*kv.z; s13 += qv.y*kv.w;
                    s20 += qv.z*kv.x; s21 += qv.z*kv.y; s22 += qv.z*kv.z; s23 += qv.z*kv.w;
                    s30 += qv.w*kv.x; s31 += qv.w*kv.y; s32 += qv.w*kv.z; s33 += qv.w*kv.w;
                }
                float* pr = Ps + (s_ty * 4) * 68 + s_tx * 4;
                pr[0]=s00; pr[1]=s01; pr[2]=s02; pr[3]=s03;  pr+=68;
                pr[0]=s10; pr[1]=s11; pr[2]=s12; pr[3]=s13;  pr+=68;
                pr[0]=s20; pr[1]=s21; pr[2]=s22; pr[3]=s23;  pr+=68;
                pr[0]=s30; pr[1]=s31; pr[2]=s32; pr[3]=s33;
            }
            __syncthreads();

            {
                float* prow = Ps + r_row * 68 + r_sub * 16;
                float4 t0 = *(const float4*)(prow + 0);
                float4 t1 = *(const float4*)(prow + 4);
                float4 t2 = *(const float4*)(prow + 8);
                float4 t3 = *(const float4*)(prow + 12);
                float tmax = fmaxf(fmaxf(fmaxf(t0.x,t0.y),fmaxf(t0.z,t0.w)),
                                   fmaxf(fmaxf(t1.x,t1.y),fmaxf(t1.z,t1.w)));
                tmax = fmaxf(tmax, fmaxf(fmaxf(t2.x,t2.y),fmaxf(t2.z,t2.w)));
                tmax = fmaxf(tmax, fmaxf(fmaxf(t3.x,t3.y),fmaxf(t3.z,t3.w)));
                tmax = fmaxf(tmax, __shfl_xor_sync(0xffffffffu, tmax, 1));
                tmax = fmaxf(tmax, __shfl_xor_sync(0xffffffffu, tmax, 2));
                float nm = fmaxf(m_, tmax);
                float corr = __expf(m_ - nm);
                t0.x=__expf(t0.x-nm); t0.y=__expf(t0.y-nm); t0.z=__expf(t0.z-nm); t0.w=__expf(t0.w-nm);
                t1.x=__expf(t1.x-nm); t1.y=__expf(t1.y-nm); t1.z=__expf(t1.z-nm); t1.w=__expf(t1.w-nm);
                t2.x=__expf(t2.x-nm); t2.y=__expf(t2.y-nm); t2.z=__expf(t2.z-nm); t2.w=__expf(t2.w-nm);
                t3.x=__expf(t3.x-nm); t3.y=__expf(t3.y-nm); t3.z=__expf(t3.z-nm); t3.w=__expf(t3.w-nm);
                float ps = (t0.x+t0.y+t0.z+t0.w) + (t1.x+t1.y+t1.z+t1.w)
                         + (t2.x+t2.y+t2.z+t2.w) + (t3.x+t3.y+t3.z+t3.w);
                ps += __shfl_xor_sync(0xffffffffu, ps, 1);
                ps += __shfl_xor_sync(0xffffffffu, ps, 2);
                l_ = l_ * corr + ps;
                m_ = nm;
                *(float4*)(prow + 0)  = t0;
                *(float4*)(prow + 4)  = t1;
                *(float4*)(prow + 8)  = t2;
                *(float4*)(prow + 12) = t3;
                if (r_sub == 0) smRow[r_row] = corr;
            }
            __syncthreads();

            {
                const float c0 = smRow[p_q];
                const float c1 = smRow[p_q + 32];
#pragma unroll
                for (int j = 0; j < 9; j++) { O[j] *= c0; O[9 + j] *= c1; }
                const float* P0 = Ps + p_q * 68;
                const float* P1 = Ps + (p_q + 32) * 68;
                const float* Vb = Vs + p_dg * 12;
#pragma unroll 4
                for (int k = 0; k < 64; k++) {
                    float a0 = P0[k], a1 = P1[k];
                    float4 v0 = *(const float4*)(Vb + k * 96);
                    float4 v1 = *(const float4*)(Vb + k * 96 + 4);
                    float  v2 = Vb[k * 96 + 8];
                    O[0] += a0*v0.x; O[1] += a0*v0.y; O[2] += a0*v0.z; O[3] += a0*v0.w;
                    O[4] += a0*v1.x; O[5] += a0*v1.y; O[6] += a0*v1.z; O[7] += a0*v1.w;
                    O[8] += a0*v2;
                    O[9]  += a1*v0.x; O[10] += a1*v0.y; O[11] += a1*v0.z; O[12] += a1*v0.w;
                    O[13] += a1*v1.x; O[14] += a1*v1.y; O[15] += a1*v1.z; O[16] += a1*v1.w;
                    O[17] += a1*v2;
                }
            }
        }

        __syncthreads();
        if (r_sub == 0) smRow[r_row] = 1.0f / l_;
        __syncthreads();
        const float i0 = smRow[p_q];
        const float i1 = smRow[p_q + 32];
        if (pass == 0) {
            float* d0 = g_xout + ((size_t)(b * SEQ + n0 + p_q)) * DIM + h * HDIM + p_dg * 9;
            float* d1 = g_xout + ((size_t)(b * SEQ + n0 + p_q + 32)) * DIM + h * HDIM + p_dg * 9;
#pragma unroll
            for (int j = 0; j < 9; j++) {
                xo[j]     = O[j] * i0;     d0[j] = xo[j];
                xo[9 + j] = O[9 + j] * i1; d1[j] = xo[9 + j];
            }
        } else {
#pragma unroll
            for (int j = 0; j < 9; j++) {
                float e0 = xo[j]     - O[j] * i0;
                float e1 = xo[9 + j] - O[9 + j] * i1;
                lsum += e0 * e0 + e1 * e1;
            }
        }
    }

    lsum *= (1.0f / TOTAL_ELEMS);
#pragma unroll
    for (int o = 16; o > 0; o >>= 1)
        lsum += __shfl_down_sync(0xffffffffu, lsum, o);
    if ((tid & 31) == 0) atomicAdd(loss_out, lsum);
}

// ---------------------------------------------------------------------------
extern "C" void kernel_launch(void* const* d_in, const int* in_sizes, int n_in,
                              void* d_out, int out_size)
{
    const float* x      = (const float*)d_in[0];
    const float* enc_k  = (const float*)d_in[1];
    const float* enc_v  = (const float*)d_in[2];
    const float* qkv_w  = (const float*)d_in[3];
    const float* qkv_b  = (const float*)d_in[4];
    const float* proj_w = (const float*)d_in[5];
    const float* proj_b = (const float*)d_in[6];
    float* out = (float*)d_out;
    float* loss_ptr = out + (out_size - 1);

    float* qkv_ptr = nullptr;
    float* xout_ptr = nullptr;
    cudaGetSymbolAddress((void**)&qkv_ptr,  g_qkv);
    cudaGetSymbolAddress((void**)&xout_ptr, g_xout);
    __nv_bfloat16 *xh, *xl, *wqh, *wql, *wph, *wpl, *oh, *ol;
    cudaGetSymbolAddress((void**)&xh,  g_xh);   cudaGetSymbolAddress((void**)&xl,  g_xl);
    cudaGetSymbolAddress((void**)&wqh, g_wqh);  cudaGetSymbolAddress((void**)&wql, g_wql);
    cudaGetSymbolAddress((void**)&wph, g_wph);  cudaGetSymbolAddress((void**)&wpl, g_wpl);
    cudaGetSymbolAddress((void**)&oh,  g_oh);   cudaGetSymbolAddress((void**)&ol,  g_ol);

    static bool attr_set = false;
    if (!attr_set) {
        cudaFuncSetAttribute(attn_kernel,
                             cudaFuncAttributeMaxDynamicSharedMemorySize, AT_SMEM_BYTES);
        cudaFuncSetAttribute(gemm_mma_kernel,
                             cudaFuncAttributeMaxDynamicSharedMemorySize, GM_SMEM_BYTES);
        attr_set = true;
    }

    cudaMemsetAsync(loss_ptr, 0, sizeof(float));

    // 0) fp32 -> bf16 hi/lo splits for GEMM inputs
    {
        int n4x = (ROWS * DIM) / 4;              // 1179648
        int n4q = (QKVN * DIM) / 4;              // 995328
        int n4p = (DIM * DIM) / 4;               // 331776
        split_bf16_kernel<<<(n4x + 255) / 256, 256>>>(x,      xh,  xl,  n4x);
        split_bf16_kernel<<<(n4q + 255) / 256, 256>>>(qkv_w,  wqh, wql, n4q);
        split_bf16_kernel<<<(n4p + 255) / 256, 256>>>(proj_w, wph, wpl, n4p);
    }

    // 1) QKV GEMM (tensor cores): (4096,1152) @ (3456,1152)^T + b -> g_qkv
    gemm_mma_kernel<<<dim3(QKVN / 128, ROWS / 128), 256, GM_SMEM_BYTES>>>(
        xh, xl, wqh, wql, qkv_b, qkv_ptr, ROWS, QKVN, DIM);

    // 2) Dual attention + loss -> g_xout, loss scalar
    attn_kernel<<<dim3(SEQ / 64, BATCH * HEADS), 256, AT_SMEM_BYTES>>>(
        enc_k, enc_v, loss_ptr);

    // 3) split attention output, then proj GEMM (tensor cores) -> out
    {
        int n4o = (ROWS * DIM) / 4;
        split_bf16_kernel<<<(n4o + 255) / 256, 256>>>(xout_ptr, oh, ol, n4o);
    }
    gemm_mma_kernel<<<dim3(DIM / 128, ROWS / 128), 256, GM_SMEM_BYTES>>>(
        oh, ol, wph, wpl, proj_b, out, ROWS, DIM, DIM);
}

// round 9
// speedup vs baseline: 2.3955x; 1.5718x over previous
#include <cuda_runtime.h>
#include <cuda_bf16.h>
#include <cstdint>
#include <cstddef>

// Problem constants (fixed by setup_inputs)
#define BATCH 4
#define SEQ   1024
#define DIM   1152
#define HEADS 16
#define HDIM  72
#define ROWS  (BATCH*SEQ)          // 4096
#define QKVN  (3*DIM)              // 3456
#define TOTAL_ELEMS 4718592.0f     // B*H*N*hd for loss mean

// Scratch (static device allocation — allowed)
__device__ __align__(16) float g_qkv [(size_t)ROWS * QKVN];   // 56.6 MB
__device__ __align__(16) float g_xout[(size_t)ROWS * DIM];    // 18.9 MB
// bf16 hi/lo split buffers
__device__ __align__(16) __nv_bfloat16 g_xh [(size_t)ROWS * DIM];
__device__ __align__(16) __nv_bfloat16 g_xl [(size_t)ROWS * DIM];
__device__ __align__(16) __nv_bfloat16 g_wqh[(size_t)QKVN * DIM];
__device__ __align__(16) __nv_bfloat16 g_wql[(size_t)QKVN * DIM];
__device__ __align__(16) __nv_bfloat16 g_wph[(size_t)DIM * DIM];
__device__ __align__(16) __nv_bfloat16 g_wpl[(size_t)DIM * DIM];
__device__ __align__(16) __nv_bfloat16 g_oh [(size_t)ROWS * DIM];
__device__ __align__(16) __nv_bfloat16 g_ol [(size_t)ROWS * DIM];

extern __shared__ char dynsm[];

// ---------------------------------------------------------------------------
// helpers
// ---------------------------------------------------------------------------
__device__ __forceinline__ void cp16(uint32_t dst, const void* src) {
    asm volatile("cp.async.cg.shared.global [%0], [%1], 16;" :: "r"(dst), "l"(src));
}
__device__ __forceinline__ void mma_bf16(float* d, const uint32_t* a, const uint32_t* b) {
    asm volatile(
        "mma.sync.aligned.m16n8k16.row.col.f32.bf16.bf16.f32 "
        "{%0,%1,%2,%3}, {%4,%5,%6,%7}, {%8,%9}, {%0,%1,%2,%3};"
        : "+f"(d[0]), "+f"(d[1]), "+f"(d[2]), "+f"(d[3])
        : "r"(a[0]), "r"(a[1]), "r"(a[2]), "r"(a[3]), "r"(b[0]), "r"(b[1]));
}
__device__ __forceinline__ void ldsm_x2_trans(uint32_t& r0, uint32_t& r1, uint32_t saddr) {
    asm volatile("ldmatrix.sync.aligned.m8n8.x2.trans.shared.b16 {%0,%1}, [%2];"
                 : "=r"(r0), "=r"(r1) : "r"(saddr));
}
// split float2 into packed bf16x2 (hi) and bf16x2 (lo residual)
__device__ __forceinline__ void split2(float x, float y, uint32_t& h, uint32_t& l) {
    __nv_bfloat16 h0 = __float2bfloat16(x);
    __nv_bfloat16 h1 = __float2bfloat16(y);
    __nv_bfloat16 l0 = __float2bfloat16(x - __bfloat162float(h0));
    __nv_bfloat16 l1 = __float2bfloat16(y - __bfloat162float(h1));
    __nv_bfloat162 hh; hh.x = h0; hh.y = h1;
    __nv_bfloat162 ll; ll.x = l0; ll.y = l1;
    h = *(uint32_t*)&hh;
    l = *(uint32_t*)&ll;
}

// ---------------------------------------------------------------------------
// fp32 -> bf16 (hi, lo) split kernel
// ---------------------------------------------------------------------------
__global__ __launch_bounds__(256)
void split_bf16_kernel(const float* __restrict__ src,
                       __nv_bfloat16* __restrict__ hi,
                       __nv_bfloat16* __restrict__ lo, int n4)
{
    int i = blockIdx.x * 256 + threadIdx.x;
    if (i >= n4) return;
    float4 v = ((const float4*)src)[i];
    uint32_t h0, l0, h1, l1;
    split2(v.x, v.y, h0, l0);
    split2(v.z, v.w, h1, l1);
    ((uint32_t*)hi)[2 * i]     = h0;
    ((uint32_t*)hi)[2 * i + 1] = h1;
    ((uint32_t*)lo)[2 * i]     = l0;
    ((uint32_t*)lo)[2 * i + 1] = l1;
}

// ---------------------------------------------------------------------------
// Tensor-core GEMM (3-term bf16 split) — unchanged from R7 (known good)
// ---------------------------------------------------------------------------
#define GM_SMEM_BYTES 81920

__global__ __launch_bounds__(256)
void gemm_mma_kernel(const __nv_bfloat16* __restrict__ Ah, const __nv_bfloat16* __restrict__ Al,
                     const __nv_bfloat16* __restrict__ Bh, const __nv_bfloat16* __restrict__ Bl,
                     const float* __restrict__ bias, float* __restrict__ C,
                     int M, int N, int K)
{
    __nv_bfloat16* sb = (__nv_bfloat16*)dynsm;
    const uint32_t sb32 = (uint32_t)__cvta_generic_to_shared(sb);

    const int tid  = threadIdx.x;
    const int warp = tid >> 5, lane = tid & 31;
    const int wm = warp >> 2, wn = warp & 3;
    const int gr = lane >> 2, c4 = lane & 3;
    const int m0 = blockIdx.y * 128, n0 = blockIdx.x * 128;

    const int l_row0 = tid >> 2,            l_cb0 = (tid & 3) << 3;
    const int l_row1 = (tid + 256) >> 2,    l_cb1 = ((tid + 256) & 3) << 3;

    float acc[4][4][4];
#pragma unroll
    for (int i = 0; i < 4; i++)
#pragma unroll
        for (int j = 0; j < 4; j++)
#pragma unroll
            for (int r = 0; r < 4; r++) acc[i][j][r] = 0.f;

    const int nkt = K >> 5;

    auto load_tile = [&](int stage, int kt) {
        const int k0 = kt << 5;
        const uint32_t st = sb32 + stage * 40960u;
        cp16(st + (uint32_t)(l_row0 * 80 + l_cb0 * 2),
             Ah + (size_t)(m0 + l_row0) * K + k0 + l_cb0);
        cp16(st + (uint32_t)(l_row1 * 80 + l_cb1 * 2),
             Ah + (size_t)(m0 + l_row1) * K + k0 + l_cb1);
        cp16(st + 10240u + (uint32_t)(l_row0 * 80 + l_cb0 * 2),
             Al + (size_t)(m0 + l_row0) * K + k0 + l_cb0);
        cp16(st + 10240u + (uint32_t)(l_row1 * 80 + l_cb1 * 2),
             Al + (size_t)(m0 + l_row1) * K + k0 + l_cb1);
        cp16(st + 20480u + (uint32_t)(l_row0 * 80 + l_cb0 * 2),
             Bh + (size_t)(n0 + l_row0) * K + k0 + l_cb0);
        cp16(st + 20480u + (uint32_t)(l_row1 * 80 + l_cb1 * 2),
             Bh + (size_t)(n0 + l_row1) * K + k0 + l_cb1);
        cp16(st + 30720u + (uint32_t)(l_row0 * 80 + l_cb0 * 2),
             Bl + (size_t)(n0 + l_row0) * K + k0 + l_cb0);
        cp16(st + 30720u + (uint32_t)(l_row1 * 80 + l_cb1 * 2),
             Bl + (size_t)(n0 + l_row1) * K + k0 + l_cb1);
        asm volatile("cp.async.commit_group;");
    };

    load_tile(0, 0);
    load_tile(1, 1);

    for (int kt = 0; kt < nkt; kt++) {
        if (kt + 1 < nkt) asm volatile("cp.async.wait_group 1;");
        else              asm volatile("cp.async.wait_group 0;");
        __syncthreads();

        const __nv_bfloat16* sAh = sb + (kt & 1) * 20480;
        const __nv_bfloat16* sAl = sAh + 5120;
        const __nv_bfloat16* sBh = sAh + 10240;
        const __nv_bfloat16* sBl = sAh + 15360;

#pragma unroll
        for (int ks = 0; ks < 2; ks++) {
            const int kb = ks * 16 + 2 * c4;
            uint32_t bh[4][2], bl[4][2];
#pragma unroll
            for (int j = 0; j < 4; j++) {
                const int nrow = wn * 32 + j * 8 + gr;
                const __nv_bfloat16* p = sBh + nrow * 40 + kb;
                const __nv_bfloat16* q = sBl + nrow * 40 + kb;
                bh[j][0] = *(const uint32_t*)p;
                bh[j][1] = *(const uint32_t*)(p + 8);
                bl[j][0] = *(const uint32_t*)q;
                bl[j][1] = *(const uint32_t*)(q + 8);
            }
#pragma unroll
            for (int i = 0; i < 4; i++) {
                const int ar = wm * 64 + i * 16 + gr;
                const __nv_bfloat16* p = sAh + ar * 40 + kb;
                const __nv_bfloat16* q = sAl + ar * 40 + kb;
                uint32_t ah[4], al[4];
                ah[0] = *(const uint32_t*)p;
                ah[1] = *(const uint32_t*)(p + 320);
                ah[2] = *(const uint32_t*)(p + 8);
                ah[3] = *(const uint32_t*)(p + 328);
                al[0] = *(const uint32_t*)q;
                al[1] = *(const uint32_t*)(q + 320);
                al[2] = *(const uint32_t*)(q + 8);
                al[3] = *(const uint32_t*)(q + 328);
#pragma unroll
                for (int j = 0; j < 4; j++) {
                    mma_bf16(acc[i][j], ah, bh[j]);
                    mma_bf16(acc[i][j], ah, bl[j]);
                    mma_bf16(acc[i][j], al, bh[j]);
                }
            }
        }
        __syncthreads();
        if (kt + 2 < nkt) load_tile(kt & 1, kt + 2);
    }

#pragma unroll
    for (int j = 0; j < 4; j++) {
        const int gn = n0 + wn * 32 + j * 8 + 2 * c4;
        const float b0 = bias[gn], b1 = bias[gn + 1];
#pragma unroll
        for (int i = 0; i < 4; i++) {
            const int gm = m0 + wm * 64 + i * 16 + gr;
            float2 w0, w1;
            w0.x = acc[i][j][0] + b0; w0.y = acc[i][j][1] + b1;
            w1.x = acc[i][j][2] + b0; w1.y = acc[i][j][3] + b1;
            *(float2*)&C[(size_t)gm * N + gn] = w0;
            *(float2*)&C[(size_t)(gm + 8) * N + gn] = w1;
        }
    }
}

// ---------------------------------------------------------------------------
// Attention v3: tensor-core scores and PV with 3-term bf16 splits.
// Block = 256 threads (8 warps), one (bh, 64-query tile) per block.
//
// smem layout (bytes):
//   sQh @0, sQl @11264, sKh @22528, sKl @33792, sVh @45056, sVl @56320
//     each [64 rows][88 bf16] (dims 0..71 data, 72..87 zero pad)
//   sPs @67584  fp32 [64][68]   (raw scores)
//   sPh @84992, sPl @94208  bf16 [64][72]  (softmaxed P, hi/lo)
//   sRow @103424 fp32 [64]      (corr / 1/l per row)
// total 103680 bytes dynamic smem.
// ---------------------------------------------------------------------------
#define AT_SMEM_BYTES 103680

__global__ __launch_bounds__(256)
void attn_kernel(const float* __restrict__ enc_k, const float* __restrict__ enc_v,
                 float* __restrict__ loss_out)
{
    __nv_bfloat16* sQh = (__nv_bfloat16*)dynsm;
    __nv_bfloat16* sQl = sQh + 5632;
    __nv_bfloat16* sKh = sQh + 11264;
    __nv_bfloat16* sKl = sQh + 16896;
    __nv_bfloat16* sVh = sQh + 22528;
    __nv_bfloat16* sVl = sQh + 28160;
    float*         sPs = (float*)(dynsm + 67584);
    __nv_bfloat16* sPh = (__nv_bfloat16*)(dynsm + 84992);
    __nv_bfloat16* sPl = (__nv_bfloat16*)(dynsm + 94208);
    float*         sRow = (float*)(dynsm + 103424);

    const int tid  = threadIdx.x;
    const int warp = tid >> 5, lane = tid & 31;
    const int gr = lane >> 2, c4 = lane & 3;
    const int wm  = warp >> 2, wn  = warp & 3;   // score warp grid 2m x 4n
    const int wm2 = warp >> 1, wn2 = warp & 1;   // PV warp grid 4m x 2n
    const int r_row = tid >> 2, r_sub = tid & 3; // softmax role

    const int bh = blockIdx.y, b = bh >> 4, h = bh & 15;
    const int n0 = blockIdx.x * 64;
    const float scale = rsqrtf((float)HDIM);

    const uint32_t vh_base = (uint32_t)__cvta_generic_to_shared(sVh);

    // ---- zero the K-dim pads (cols 72..87) of all six bf16 arrays ----
    for (int i = tid; i < 6 * 64 * 8; i += 256) {
        int arr = i >> 9, rem = i & 511;
        int row = rem >> 3, cp = rem & 7;
        *(uint32_t*)(sQh + arr * 5632 + row * 88 + 72 + 2 * cp) = 0;
    }

    // ---- load Q tile (scaled), split to hi/lo ----
    {
        const float* qbase = g_qkv + ((size_t)(b * SEQ + n0)) * QKVN + h * HDIM;
#pragma unroll
        for (int r = 0; r < 9; r++) {
            int e = tid + r * 256;
            int q = e / 36, dp = e - q * 36, d = dp * 2;
            float2 v = *(const float2*)(qbase + (size_t)q * QKVN + d);
            uint32_t hh, ll;
            split2(v.x * scale, v.y * scale, hh, ll);
            *(uint32_t*)(sQh + q * 88 + d) = hh;
            *(uint32_t*)(sQl + q * 88 + d) = ll;
        }
    }

    float xo[20];
    float lsum = 0.f;

    for (int pass = 0; pass < 2; pass++) {
        float m_ = -1e30f, l_ = 0.f;    // softmax-role stats (row r_row)
        float oacc[5][4];
#pragma unroll
        for (int j = 0; j < 5; j++)
#pragma unroll
            for (int r = 0; r < 4; r++) oacc[j][r] = 0.f;

#pragma unroll 1
        for (int kt = 0; kt < 16; kt++) {
            __syncthreads();    // smem free from previous tile / Q stores done

            // ---- load K,V fp32 -> split -> smem bf16 ----
            if (pass == 0) {
                const float* kb = g_qkv + ((size_t)(b * SEQ + kt * 64)) * QKVN + DIM + h * HDIM;
                const float* vb = kb + DIM;
#pragma unroll
                for (int r = 0; r < 9; r++) {
                    int e = tid + r * 256;
                    int key = e / 36, dp = e - key * 36, d = dp * 2;
                    float2 kv = *(const float2*)(kb + (size_t)key * QKVN + d);
                    float2 vv = *(const float2*)(vb + (size_t)key * QKVN + d);
                    uint32_t hh, ll;
                    split2(kv.x, kv.y, hh, ll);
                    *(uint32_t*)(sKh + key * 88 + d) = hh;
                    *(uint32_t*)(sKl + key * 88 + d) = ll;
                    split2(vv.x, vv.y, hh, ll);
                    *(uint32_t*)(sVh + key * 88 + d) = hh;
                    *(uint32_t*)(sVl + key * 88 + d) = ll;
                }
            } else {
                const float* kb = enc_k + ((size_t)bh * SEQ + kt * 64) * HDIM;
                const float* vb = enc_v + ((size_t)bh * SEQ + kt * 64) * HDIM;
#pragma unroll
                for (int r = 0; r < 9; r++) {
                    int e = tid + r * 256;
                    int key = e / 36, dp = e - key * 36, d = dp * 2;
                    float2 kv = *(const float2*)(kb + (size_t)key * HDIM + d);
                    float2 vv = *(const float2*)(vb + (size_t)key * HDIM + d);
                    uint32_t hh, ll;
                    split2(kv.x, kv.y, hh, ll);
                    *(uint32_t*)(sKh + key * 88 + d) = hh;
                    *(uint32_t*)(sKl + key * 88 + d) = ll;
                    split2(vv.x, vv.y, hh, ll);
                    *(uint32_t*)(sVh + key * 88 + d) = hh;
                    *(uint32_t*)(sVl + key * 88 + d) = ll;
                }
            }
            __syncthreads();

            // ---- scores: S = Q K^T via MMA (3 terms), K dims padded to 80 ----
            {
                float sacc[2][2][4];
#pragma unroll
                for (int i = 0; i < 2; i++)
#pragma unroll
                    for (int j = 0; j < 2; j++)
#pragma unroll
                        for (int r = 0; r < 4; r++) sacc[i][j][r] = 0.f;

#pragma unroll
                for (int ks = 0; ks < 5; ks++) {
                    const int kb = ks * 16 + 2 * c4;
                    uint32_t bh2[2][2], bl2[2][2];
#pragma unroll
                    for (int j = 0; j < 2; j++) {
                        const int nr = wn * 16 + j * 8 + gr;
                        const __nv_bfloat16* p = sKh + nr * 88 + kb;
                        const __nv_bfloat16* q = sKl + nr * 88 + kb;
                        bh2[j][0] = *(const uint32_t*)p;
                        bh2[j][1] = *(const uint32_t*)(p + 8);
                        bl2[j][0] = *(const uint32_t*)q;
                        bl2[j][1] = *(const uint32_t*)(q + 8);
                    }
#pragma unroll
                    for (int i = 0; i < 2; i++) {
                        const int ar = wm * 32 + i * 16 + gr;
                        const __nv_bfloat16* p = sQh + ar * 88 + kb;
                        const __nv_bfloat16* q = sQl + ar * 88 + kb;
                        uint32_t ah[4], al[4];
                        ah[0] = *(const uint32_t*)p;
                        ah[1] = *(const uint32_t*)(p + 8 * 88);
                        ah[2] = *(const uint32_t*)(p + 8);
                        ah[3] = *(const uint32_t*)(p + 8 * 88 + 8);
                        al[0] = *(const uint32_t*)q;
                        al[1] = *(const uint32_t*)(q + 8 * 88);
                        al[2] = *(const uint32_t*)(q + 8);
                        al[3] = *(const uint32_t*)(q + 8 * 88 + 8);
#pragma unroll
                        for (int j = 0; j < 2; j++) {
                            mma_bf16(sacc[i][j], ah, bh2[j]);
                            mma_bf16(sacc[i][j], ah, bl2[j]);
                            mma_bf16(sacc[i][j], al, bh2[j]);
                        }
                    }
                }
                // store raw scores to Ps (fp32, stride 68)
#pragma unroll
                for (int i = 0; i < 2; i++)
#pragma unroll
                    for (int j = 0; j < 2; j++) {
                        const int row = wm * 32 + i * 16 + gr;
                        const int col = wn * 16 + j * 8 + 2 * c4;
                        *(float2*)&sPs[row * 68 + col] =
                            make_float2(sacc[i][j][0], sacc[i][j][1]);
                        *(float2*)&sPs[(row + 8) * 68 + col] =
                            make_float2(sacc[i][j][2], sacc[i][j][3]);
                    }
            }
            __syncthreads();

            // ---- softmax (row r_row, cols r_sub*16..+15), emit Ph/Pl bf16 ----
            {
                const float* prow = sPs + r_row * 68 + r_sub * 16;
                float4 t0 = *(const float4*)(prow + 0);
                float4 t1 = *(const float4*)(prow + 4);
                float4 t2 = *(const float4*)(prow + 8);
                float4 t3 = *(const float4*)(prow + 12);
                float tmax = fmaxf(fmaxf(fmaxf(t0.x,t0.y),fmaxf(t0.z,t0.w)),
                                   fmaxf(fmaxf(t1.x,t1.y),fmaxf(t1.z,t1.w)));
                tmax = fmaxf(tmax, fmaxf(fmaxf(t2.x,t2.y),fmaxf(t2.z,t2.w)));
                tmax = fmaxf(tmax, fmaxf(fmaxf(t3.x,t3.y),fmaxf(t3.z,t3.w)));
                tmax = fmaxf(tmax, __shfl_xor_sync(0xffffffffu, tmax, 1));
                tmax = fmaxf(tmax, __shfl_xor_sync(0xffffffffu, tmax, 2));
                float nm = fmaxf(m_, tmax);
                float corr = __expf(m_ - nm);
                t0.x=__expf(t0.x-nm); t0.y=__expf(t0.y-nm); t0.z=__expf(t0.z-nm); t0.w=__expf(t0.w-nm);
                t1.x=__expf(t1.x-nm); t1.y=__expf(t1.y-nm); t1.z=__expf(t1.z-nm); t1.w=__expf(t1.w-nm);
                t2.x=__expf(t2.x-nm); t2.y=__expf(t2.y-nm); t2.z=__expf(t2.z-nm); t2.w=__expf(t2.w-nm);
                t3.x=__expf(t3.x-nm); t3.y=__expf(t3.y-nm); t3.z=__expf(t3.z-nm); t3.w=__expf(t3.w-nm);
                float ps = (t0.x+t0.y+t0.z+t0.w) + (t1.x+t1.y+t1.z+t1.w)
                         + (t2.x+t2.y+t2.z+t2.w) + (t3.x+t3.y+t3.z+t3.w);
                ps += __shfl_xor_sync(0xffffffffu, ps, 1);
                ps += __shfl_xor_sync(0xffffffffu, ps, 2);
                l_ = l_ * corr + ps;
                m_ = nm;

                __nv_bfloat16* ph = sPh + r_row * 72 + r_sub * 16;
                __nv_bfloat16* pl = sPl + r_row * 72 + r_sub * 16;
                uint32_t hh, ll;
                split2(t0.x, t0.y, hh, ll); *(uint32_t*)(ph+ 0)=hh; *(uint32_t*)(pl+ 0)=ll;
                split2(t0.z, t0.w, hh, ll); *(uint32_t*)(ph+ 2)=hh; *(uint32_t*)(pl+ 2)=ll;
                split2(t1.x, t1.y, hh, ll); *(uint32_t*)(ph+ 4)=hh; *(uint32_t*)(pl+ 4)=ll;
                split2(t1.z, t1.w, hh, ll); *(uint32_t*)(ph+ 6)=hh; *(uint32_t*)(pl+ 6)=ll;
                split2(t2.x, t2.y, hh, ll); *(uint32_t*)(ph+ 8)=hh; *(uint32_t*)(pl+ 8)=ll;
                split2(t2.z, t2.w, hh, ll); *(uint32_t*)(ph+10)=hh; *(uint32_t*)(pl+10)=ll;
                split2(t3.x, t3.y, hh, ll); *(uint32_t*)(ph+12)=hh; *(uint32_t*)(pl+12)=ll;
                split2(t3.z, t3.w, hh, ll); *(uint32_t*)(ph+14)=hh; *(uint32_t*)(pl+14)=ll;
                if (r_sub == 0) sRow[r_row] = corr;
            }
            __syncthreads();

            // ---- PV: O = corr*O + P V via MMA (3 terms) ----
            {
                const float cr0 = sRow[wm2 * 16 + gr];
                const float cr1 = sRow[wm2 * 16 + gr + 8];
#pragma unroll
                for (int j = 0; j < 5; j++) {
                    oacc[j][0] *= cr0; oacc[j][1] *= cr0;
                    oacc[j][2] *= cr1; oacc[j][3] *= cr1;
                }
#pragma unroll
                for (int ks = 0; ks < 4; ks++) {
                    const __nv_bfloat16* p = sPh + (wm2 * 16 + gr) * 72 + ks * 16 + 2 * c4;
                    const __nv_bfloat16* q = sPl + (wm2 * 16 + gr) * 72 + ks * 16 + 2 * c4;
                    uint32_t ph[4], pl[4];
                    ph[0] = *(const uint32_t*)p;
                    ph[1] = *(const uint32_t*)(p + 8 * 72);
                    ph[2] = *(const uint32_t*)(p + 8);
                    ph[3] = *(const uint32_t*)(p + 8 * 72 + 8);
                    pl[0] = *(const uint32_t*)q;
                    pl[1] = *(const uint32_t*)(q + 8 * 72);
                    pl[2] = *(const uint32_t*)(q + 8);
                    pl[3] = *(const uint32_t*)(q + 8 * 72 + 8);
                    const uint32_t rowb = vh_base +
                        (uint32_t)(((ks * 16 + (lane & 15)) * 88) * 2);
#pragma unroll
                    for (int j = 0; j < 5; j++) {
                        const uint32_t va = rowb + (uint32_t)((wn2 * 40 + j * 8) * 2);
                        uint32_t vh2[2], vl2[2];
                        ldsm_x2_trans(vh2[0], vh2[1], va);
                        ldsm_x2_trans(vl2[0], vl2[1], va + 11264u);
                        mma_bf16(oacc[j], ph, vh2);
                        mma_bf16(oacc[j], ph, vl2);
                        mma_bf16(oacc[j], pl, vh2);
                    }
                }
            }
        }

        // ---- pass epilogue ----
        __syncthreads();
        if (r_sub == 0) sRow[r_row] = 1.0f / l_;
        __syncthreads();
        const float i0 = sRow[wm2 * 16 + gr];
        const float i1 = sRow[wm2 * 16 + gr + 8];
        if (pass == 0) {
            const int q0 = n0 + wm2 * 16 + gr;
#pragma unroll
            for (int j = 0; j < 5; j++) {
                const int dim = wn2 * 40 + j * 8 + 2 * c4;
                xo[j*4+0] = oacc[j][0] * i0; xo[j*4+1] = oacc[j][1] * i0;
                xo[j*4+2] = oacc[j][2] * i1; xo[j*4+3] = oacc[j][3] * i1;
                if (dim < 72) {
                    float* d0 = g_xout + ((size_t)(b * SEQ + q0)) * DIM + h * HDIM + dim;
                    float* d1 = g_xout + ((size_t)(b * SEQ + q0 + 8)) * DIM + h * HDIM + dim;
                    *(float2*)d0 = make_float2(xo[j*4+0], xo[j*4+1]);
                    *(float2*)d1 = make_float2(xo[j*4+2], xo[j*4+3]);
                }
            }
        } else {
#pragma unroll
            for (int j = 0; j < 5; j++) {
                const int dim = wn2 * 40 + j * 8 + 2 * c4;
                if (dim < 72) {
                    float e0 = xo[j*4+0] - oacc[j][0] * i0;
                    float e1 = xo[j*4+1] - oacc[j][1] * i0;
                    float e2 = xo[j*4+2] - oacc[j][2] * i1;
                    float e3 = xo[j*4+3] - oacc[j][3] * i1;
                    lsum += e0*e0 + e1*e1 + e2*e2 + e3*e3;
                }
            }
        }
    }

    // loss reduction: warp reduce + one atomic per warp
    lsum *= (1.0f / TOTAL_ELEMS);
#pragma unroll
    for (int o = 16; o > 0; o >>= 1)
        lsum += __shfl_down_sync(0xffffffffu, lsum, o);
    if (lane == 0) atomicAdd(loss_out, lsum);
}

// ---------------------------------------------------------------------------
extern "C" void kernel_launch(void* const* d_in, const int* in_sizes, int n_in,
                              void* d_out, int out_size)
{
    const float* x      = (const float*)d_in[0];
    const float* enc_k  = (const float*)d_in[1];
    const float* enc_v  = (const float*)d_in[2];
    const float* qkv_w  = (const float*)d_in[3];
    const float* qkv_b  = (const float*)d_in[4];
    const float* proj_w = (const float*)d_in[5];
    const float* proj_b = (const float*)d_in[6];
    float* out = (float*)d_out;
    float* loss_ptr = out + (out_size - 1);

    float* qkv_ptr = nullptr;
    float* xout_ptr = nullptr;
    cudaGetSymbolAddress((void**)&qkv_ptr,  g_qkv);
    cudaGetSymbolAddress((void**)&xout_ptr, g_xout);
    __nv_bfloat16 *xh, *xl, *wqh, *wql, *wph, *wpl, *oh, *ol;
    cudaGetSymbolAddress((void**)&xh,  g_xh);   cudaGetSymbolAddress((void**)&xl,  g_xl);
    cudaGetSymbolAddress((void**)&wqh, g_wqh);  cudaGetSymbolAddress((void**)&wql, g_wql);
    cudaGetSymbolAddress((void**)&wph, g_wph);  cudaGetSymbolAddress((void**)&wpl, g_wpl);
    cudaGetSymbolAddress((void**)&oh,  g_oh);   cudaGetSymbolAddress((void**)&ol,  g_ol);

    static bool attr_set = false;
    if (!attr_set) {
        cudaFuncSetAttribute(attn_kernel,
                             cudaFuncAttributeMaxDynamicSharedMemorySize, AT_SMEM_BYTES);
        cudaFuncSetAttribute(gemm_mma_kernel,
                             cudaFuncAttributeMaxDynamicSharedMemorySize, GM_SMEM_BYTES);
        attr_set = true;
    }

    cudaMemsetAsync(loss_ptr, 0, sizeof(float));

    // 0) fp32 -> bf16 hi/lo splits for GEMM inputs
    {
        int n4x = (ROWS * DIM) / 4;
        int n4q = (QKVN * DIM) / 4;
        int n4p = (DIM * DIM) / 4;
        split_bf16_kernel<<<(n4x + 255) / 256, 256>>>(x,      xh,  xl,  n4x);
        split_bf16_kernel<<<(n4q + 255) / 256, 256>>>(qkv_w,  wqh, wql, n4q);
        split_bf16_kernel<<<(n4p + 255) / 256, 256>>>(proj_w, wph, wpl, n4p);
    }

    // 1) QKV GEMM (tensor cores)
    gemm_mma_kernel<<<dim3(QKVN / 128, ROWS / 128), 256, GM_SMEM_BYTES>>>(
        xh, xl, wqh, wql, qkv_b, qkv_ptr, ROWS, QKVN, DIM);

    // 2) Dual attention + loss (tensor cores)
    attn_kernel<<<dim3(SEQ / 64, BATCH * HEADS), 256, AT_SMEM_BYTES>>>(
        enc_k, enc_v, loss_ptr);

    // 3) split attention output, then proj GEMM (tensor cores)
    {
        int n4o = (ROWS * DIM) / 4;
        split_bf16_kernel<<<(n4o + 255) / 256, 256>>>(xout_ptr, oh, ol, n4o);
    }
    gemm_mma_kernel<<<dim3(DIM / 128, ROWS / 128), 256, GM_SMEM_BYTES>>>(
        oh, ol, wph, wpl, proj_b, out, ROWS, DIM, DIM);
}

// round 10
// speedup vs baseline: 2.8321x; 1.1822x over previous
#include <cuda_runtime.h>
#include <cuda_bf16.h>
#include <cstdint>
#include <cstddef>

// Problem constants (fixed by setup_inputs)
#define BATCH 4
#define SEQ   1024
#define DIM   1152
#define HEADS 16
#define HDIM  72
#define ROWS  (BATCH*SEQ)          // 4096
#define QKVN  (3*DIM)              // 3456
#define TOTAL_ELEMS 4718592.0f     // B*H*N*hd for loss mean
#define QSCALE 0.11785113f         // 72^-0.5

// Scratch (static device allocation — allowed). All bf16 hi/lo pairs.
__device__ __align__(16) __nv_bfloat16 g_xh [(size_t)ROWS * DIM];
__device__ __align__(16) __nv_bfloat16 g_xl [(size_t)ROWS * DIM];
__device__ __align__(16) __nv_bfloat16 g_wqh[(size_t)QKVN * DIM];
__device__ __align__(16) __nv_bfloat16 g_wql[(size_t)QKVN * DIM];
__device__ __align__(16) __nv_bfloat16 g_wph[(size_t)DIM * DIM];
__device__ __align__(16) __nv_bfloat16 g_wpl[(size_t)DIM * DIM];
// head-major [bh][seq][72] bf16 Q/K/V (hi/lo), written by QKV GEMM epilogue
__device__ __align__(16) __nv_bfloat16 g_qh [(size_t)ROWS * DIM];
__device__ __align__(16) __nv_bfloat16 g_ql [(size_t)ROWS * DIM];
__device__ __align__(16) __nv_bfloat16 g_kh [(size_t)ROWS * DIM];
__device__ __align__(16) __nv_bfloat16 g_kl [(size_t)ROWS * DIM];
__device__ __align__(16) __nv_bfloat16 g_vh [(size_t)ROWS * DIM];
__device__ __align__(16) __nv_bfloat16 g_vl [(size_t)ROWS * DIM];
// encoder K/V pre-split (same [bh][seq][72] layout as the fp32 inputs)
__device__ __align__(16) __nv_bfloat16 g_ekh[(size_t)ROWS * DIM];
__device__ __align__(16) __nv_bfloat16 g_ekl[(size_t)ROWS * DIM];
__device__ __align__(16) __nv_bfloat16 g_evh[(size_t)ROWS * DIM];
__device__ __align__(16) __nv_bfloat16 g_evl[(size_t)ROWS * DIM];
// attention output (hi/lo) -> proj GEMM input
__device__ __align__(16) __nv_bfloat16 g_oh [(size_t)ROWS * DIM];
__device__ __align__(16) __nv_bfloat16 g_ol [(size_t)ROWS * DIM];

extern __shared__ char dynsm[];

// ---------------------------------------------------------------------------
// helpers
// ---------------------------------------------------------------------------
__device__ __forceinline__ void cp16(uint32_t dst, const void* src) {
    asm volatile("cp.async.cg.shared.global [%0], [%1], 16;" :: "r"(dst), "l"(src));
}
__device__ __forceinline__ void mma_bf16(float* d, const uint32_t* a, const uint32_t* b) {
    asm volatile(
        "mma.sync.aligned.m16n8k16.row.col.f32.bf16.bf16.f32 "
        "{%0,%1,%2,%3}, {%4,%5,%6,%7}, {%8,%9}, {%0,%1,%2,%3};"
        : "+f"(d[0]), "+f"(d[1]), "+f"(d[2]), "+f"(d[3])
        : "r"(a[0]), "r"(a[1]), "r"(a[2]), "r"(a[3]), "r"(b[0]), "r"(b[1]));
}
__device__ __forceinline__ void ldsm_x2_trans(uint32_t& r0, uint32_t& r1, uint32_t saddr) {
    asm volatile("ldmatrix.sync.aligned.m8n8.x2.trans.shared.b16 {%0,%1}, [%2];"
                 : "=r"(r0), "=r"(r1) : "r"(saddr));
}
__device__ __forceinline__ void split2(float x, float y, uint32_t& h, uint32_t& l) {
    __nv_bfloat16 h0 = __float2bfloat16(x);
    __nv_bfloat16 h1 = __float2bfloat16(y);
    __nv_bfloat16 l0 = __float2bfloat16(x - __bfloat162float(h0));
    __nv_bfloat16 l1 = __float2bfloat16(y - __bfloat162float(h1));
    __nv_bfloat162 hh; hh.x = h0; hh.y = h1;
    __nv_bfloat162 ll; ll.x = l0; ll.y = l1;
    h = *(uint32_t*)&hh;
    l = *(uint32_t*)&ll;
}

// ---------------------------------------------------------------------------
// fp32 -> bf16 (hi, lo) split kernel
// ---------------------------------------------------------------------------
__global__ __launch_bounds__(256)
void split_bf16_kernel(const float* __restrict__ src,
                       __nv_bfloat16* __restrict__ hi,
                       __nv_bfloat16* __restrict__ lo, int n4)
{
    int i = blockIdx.x * 256 + threadIdx.x;
    if (i >= n4) return;
    float4 v = ((const float4*)src)[i];
    uint32_t h0, l0, h1, l1;
    split2(v.x, v.y, h0, l0);
    split2(v.z, v.w, h1, l1);
    ((uint32_t*)hi)[2 * i]     = h0;
    ((uint32_t*)hi)[2 * i + 1] = h1;
    ((uint32_t*)lo)[2 * i]     = l0;
    ((uint32_t*)lo)[2 * i + 1] = l1;
}

// ---------------------------------------------------------------------------
// Tensor-core GEMM (3-term bf16 split). EPI=0: fp32 C (+bias). EPI=1: QKV
// epilogue — bias, head-major remap, q-scaling, bf16 hi/lo split stores.
// ---------------------------------------------------------------------------
#define GM_SMEM_BYTES 81920

template<int EPI>
__global__ __launch_bounds__(256, 2)
void gemm_mma_kernel(const __nv_bfloat16* __restrict__ Ah, const __nv_bfloat16* __restrict__ Al,
                     const __nv_bfloat16* __restrict__ Bh, const __nv_bfloat16* __restrict__ Bl,
                     const float* __restrict__ bias, float* __restrict__ C,
                     int M, int N, int K)
{
    __nv_bfloat16* sb = (__nv_bfloat16*)dynsm;
    const uint32_t sb32 = (uint32_t)__cvta_generic_to_shared(sb);

    const int tid  = threadIdx.x;
    const int warp = tid >> 5, lane = tid & 31;
    const int wm = warp >> 2, wn = warp & 3;
    const int gr = lane >> 2, c4 = lane & 3;
    const int m0 = blockIdx.y * 128, n0 = blockIdx.x * 128;

    const int l_row0 = tid >> 2,            l_cb0 = (tid & 3) << 3;
    const int l_row1 = (tid + 256) >> 2,    l_cb1 = ((tid + 256) & 3) << 3;

    float acc[4][4][4];
#pragma unroll
    for (int i = 0; i < 4; i++)
#pragma unroll
        for (int j = 0; j < 4; j++)
#pragma unroll
            for (int r = 0; r < 4; r++) acc[i][j][r] = 0.f;

    const int nkt = K >> 5;

    auto load_tile = [&](int stage, int kt) {
        const int k0 = kt << 5;
        const uint32_t st = sb32 + stage * 40960u;
        cp16(st + (uint32_t)(l_row0 * 80 + l_cb0 * 2),
             Ah + (size_t)(m0 + l_row0) * K + k0 + l_cb0);
        cp16(st + (uint32_t)(l_row1 * 80 + l_cb1 * 2),
             Ah + (size_t)(m0 + l_row1) * K + k0 + l_cb1);
        cp16(st + 10240u + (uint32_t)(l_row0 * 80 + l_cb0 * 2),
             Al + (size_t)(m0 + l_row0) * K + k0 + l_cb0);
        cp16(st + 10240u + (uint32_t)(l_row1 * 80 + l_cb1 * 2),
             Al + (size_t)(m0 + l_row1) * K + k0 + l_cb1);
        cp16(st + 20480u + (uint32_t)(l_row0 * 80 + l_cb0 * 2),
             Bh + (size_t)(n0 + l_row0) * K + k0 + l_cb0);
        cp16(st + 20480u + (uint32_t)(l_row1 * 80 + l_cb1 * 2),
             Bh + (size_t)(n0 + l_row1) * K + k0 + l_cb1);
        cp16(st + 30720u + (uint32_t)(l_row0 * 80 + l_cb0 * 2),
             Bl + (size_t)(n0 + l_row0) * K + k0 + l_cb0);
        cp16(st + 30720u + (uint32_t)(l_row1 * 80 + l_cb1 * 2),
             Bl + (size_t)(n0 + l_row1) * K + k0 + l_cb1);
        asm volatile("cp.async.commit_group;");
    };

    load_tile(0, 0);
    load_tile(1, 1);

    for (int kt = 0; kt < nkt; kt++) {
        if (kt + 1 < nkt) asm volatile("cp.async.wait_group 1;");
        else              asm volatile("cp.async.wait_group 0;");
        __syncthreads();

        const __nv_bfloat16* sAh = sb + (kt & 1) * 20480;
        const __nv_bfloat16* sAl = sAh + 5120;
        const __nv_bfloat16* sBh = sAh + 10240;
        const __nv_bfloat16* sBl = sAh + 15360;

#pragma unroll
        for (int ks = 0; ks < 2; ks++) {
            const int kb = ks * 16 + 2 * c4;
            uint32_t bh[4][2], bl[4][2];
#pragma unroll
            for (int j = 0; j < 4; j++) {
                const int nrow = wn * 32 + j * 8 + gr;
                const __nv_bfloat16* p = sBh + nrow * 40 + kb;
                const __nv_bfloat16* q = sBl + nrow * 40 + kb;
                bh[j][0] = *(const uint32_t*)p;
                bh[j][1] = *(const uint32_t*)(p + 8);
                bl[j][0] = *(const uint32_t*)q;
                bl[j][1] = *(const uint32_t*)(q + 8);
            }
#pragma unroll
            for (int i = 0; i < 4; i++) {
                const int ar = wm * 64 + i * 16 + gr;
                const __nv_bfloat16* p = sAh + ar * 40 + kb;
                const __nv_bfloat16* q = sAl + ar * 40 + kb;
                uint32_t ah[4], al[4];
                ah[0] = *(const uint32_t*)p;
                ah[1] = *(const uint32_t*)(p + 320);
                ah[2] = *(const uint32_t*)(p + 8);
                ah[3] = *(const uint32_t*)(p + 328);
                al[0] = *(const uint32_t*)q;
                al[1] = *(const uint32_t*)(q + 320);
                al[2] = *(const uint32_t*)(q + 8);
                al[3] = *(const uint32_t*)(q + 328);
#pragma unroll
                for (int j = 0; j < 4; j++) {
                    mma_bf16(acc[i][j], ah, bh[j]);
                    mma_bf16(acc[i][j], ah, bl[j]);
                    mma_bf16(acc[i][j], al, bh[j]);
                }
            }
        }
        __syncthreads();
        if (kt + 2 < nkt) load_tile(kt & 1, kt + 2);
    }

#pragma unroll
    for (int j = 0; j < 4; j++) {
        const int gn = n0 + wn * 32 + j * 8 + 2 * c4;
        const float b0 = bias[gn], b1 = bias[gn + 1];
        if (EPI == 0) {
#pragma unroll
            for (int i = 0; i < 4; i++) {
                const int gm = m0 + wm * 64 + i * 16 + gr;
                float2 w0, w1;
                w0.x = acc[i][j][0] + b0; w0.y = acc[i][j][1] + b1;
                w1.x = acc[i][j][2] + b0; w1.y = acc[i][j][3] + b1;
                *(float2*)&C[(size_t)gm * N + gn] = w0;
                *(float2*)&C[(size_t)(gm + 8) * N + gn] = w1;
            }
        } else {
            // QKV epilogue: part (q/k/v), head-major [bh][seq][72] bf16 hi/lo
            const int part = gn / DIM;
            const int rem  = gn - part * DIM;
            const int hh   = rem / HDIM;
            const int dd   = rem - hh * HDIM;          // even
            uint32_t* dsth;
            uint32_t* dstl;
            float sc = 1.f;
            if (part == 0)      { dsth = (uint32_t*)g_qh; dstl = (uint32_t*)g_ql; sc = QSCALE; }
            else if (part == 1) { dsth = (uint32_t*)g_kh; dstl = (uint32_t*)g_kl; }
            else                { dsth = (uint32_t*)g_vh; dstl = (uint32_t*)g_vl; }
#pragma unroll
            for (int i = 0; i < 4; i++) {
                const int gm = m0 + wm * 64 + i * 16 + gr;
                const int b_ = gm >> 10, seq = gm & 1023;
                const size_t idx = (((size_t)(b_ * HEADS + hh) << 10) + seq) * 36 + (dd >> 1);
                uint32_t h_, l_;
                split2((acc[i][j][0] + b0) * sc, (acc[i][j][1] + b1) * sc, h_, l_);
                dsth[idx] = h_; dstl[idx] = l_;
                split2((acc[i][j][2] + b0) * sc, (acc[i][j][3] + b1) * sc, h_, l_);
                dsth[idx + 8 * 36] = h_; dstl[idx + 8 * 36] = l_;
            }
        }
    }
}

// ---------------------------------------------------------------------------
// Attention v4: tensor-core scores/PV (3-term bf16), pre-split bf16 inputs,
// cp.async double-buffered K/V tiles.
//
// smem (bytes):
//   sQh @0, sQl @11264                       (each [64][88] bf16)
//   KV  @22528: 2 bufs x {Kh,Kl,Vh,Vl}       (each [64][88] bf16, 11264 B)
//   sPs @112640  fp32 [64][68]
//   sPh @130048, sPl @139264  bf16 [64][72]
//   sRow @148480 fp32 [64]   -> total 148736
// ---------------------------------------------------------------------------
#define AT_SMEM_BYTES 148736

__global__ __launch_bounds__(256)
void attn_kernel(float* __restrict__ loss_out)
{
    __nv_bfloat16* smbf = (__nv_bfloat16*)dynsm;
    __nv_bfloat16* sQh = smbf;
    __nv_bfloat16* sQl = smbf + 5632;
    float*         sPs = (float*)(dynsm + 112640);
    __nv_bfloat16* sPh = (__nv_bfloat16*)(dynsm + 130048);
    __nv_bfloat16* sPl = (__nv_bfloat16*)(dynsm + 139264);
    float*         sRow = (float*)(dynsm + 148480);

    const uint32_t smu   = (uint32_t)__cvta_generic_to_shared(smbf);
    const uint32_t kvb32 = smu + 22528u;

    const int tid  = threadIdx.x;
    const int warp = tid >> 5, lane = tid & 31;
    const int gr = lane >> 2, c4 = lane & 3;
    const int wm  = warp >> 2, wn  = warp & 3;   // score grid 2m x 4n
    const int wm2 = warp >> 1, wn2 = warp & 1;   // PV grid 4m x 2n
    const int r_row = tid >> 2, r_sub = tid & 3; // softmax role

    const int bh = blockIdx.y, b = bh >> 4, h = bh & 15;
    const int n0 = blockIdx.x * 64;

    // ---- prefetch K/V tile 0 (buf 0) ----
    auto prefetch = [&](int t, int buf) {
        const int kt = t & 15;
        const __nv_bfloat16* s0 = (t < 16) ? g_kh : g_ekh;
        const __nv_bfloat16* s1 = (t < 16) ? g_kl : g_ekl;
        const __nv_bfloat16* s2 = (t < 16) ? g_vh : g_evh;
        const __nv_bfloat16* s3 = (t < 16) ? g_vl : g_evl;
        const size_t toff = (((size_t)bh << 10) + kt * 64) * HDIM;
#pragma unroll
        for (int r = 0; r < 9; r++) {
            int e = tid + r * 256;               // 0..2303
            int arr = e / 576, rem = e - arr * 576;
            int row = rem / 9,  ch  = rem - row * 9;
            const __nv_bfloat16* src =
                (arr == 0 ? s0 : arr == 1 ? s1 : arr == 2 ? s2 : s3)
                + toff + row * HDIM + ch * 8;
            cp16(kvb32 + buf * 45056u + arr * 11264u
                       + (uint32_t)(row * 176 + ch * 16), src);
        }
        asm volatile("cp.async.commit_group;");
    };
    prefetch(0, 0);

    // ---- zero pads (cols 72..87) of the 10 bf16 arrays (uniform 5632 stride) ----
    for (int i = tid; i < 10 * 64 * 8; i += 256) {
        int arr = i >> 9, rem = i & 511;
        int row = rem >> 3, cp = rem & 7;
        *(uint32_t*)(smbf + arr * 5632 + row * 88 + 72 + 2 * cp) = 0;
    }

    // ---- load Q tile (bf16 hi/lo, pre-scaled) ----
    {
        const uint32_t* qh = (const uint32_t*)g_qh;
        const uint32_t* ql = (const uint32_t*)g_ql;
        const size_t qoff = (((size_t)bh << 10) + n0) * 36;
#pragma unroll
        for (int r = 0; r < 9; r++) {
            int e = tid + r * 256;               // 0..2303
            int row = e / 36, ch = e - row * 36;
            size_t gi = qoff + row * 36 + ch;
            *(uint32_t*)(sQh + row * 88 + ch * 2) = qh[gi];
            *(uint32_t*)(sQl + row * 88 + ch * 2) = ql[gi];
        }
    }

    float xo[20];
    float lsum = 0.f;
    float m_ = -1e30f, l_ = 0.f;
    float oacc[5][4];
#pragma unroll
    for (int j = 0; j < 5; j++)
#pragma unroll
        for (int r = 0; r < 4; r++) oacc[j][r] = 0.f;

#pragma unroll 1
    for (int t = 0; t < 32; t++) {
        const int buf = t & 1;
        const int pass = t >> 4;

        // pass boundary: reset online-softmax state (epilogue handled below)
        asm volatile("cp.async.wait_group 0;");
        __syncthreads();
        if (t + 1 < 32) prefetch(t + 1, buf ^ 1);

        const __nv_bfloat16* sKh = smbf + 11264 + buf * 22528;
        const __nv_bfloat16* sKl = sKh + 5632;
        const uint32_t vh_base = kvb32 + buf * 45056u + 22528u;

        // ---- scores: S = Q K^T via MMA (3 terms) ----
        {
            float sacc[2][2][4];
#pragma unroll
            for (int i = 0; i < 2; i++)
#pragma unroll
                for (int j = 0; j < 2; j++)
#pragma unroll
                    for (int r = 0; r < 4; r++) sacc[i][j][r] = 0.f;

#pragma unroll
            for (int ks = 0; ks < 5; ks++) {
                const int kb = ks * 16 + 2 * c4;
                uint32_t bh2[2][2], bl2[2][2];
#pragma unroll
                for (int j = 0; j < 2; j++) {
                    const int nr = wn * 16 + j * 8 + gr;
                    const __nv_bfloat16* p = sKh + nr * 88 + kb;
                    const __nv_bfloat16* q = sKl + nr * 88 + kb;
                    bh2[j][0] = *(const uint32_t*)p;
                    bh2[j][1] = *(const uint32_t*)(p + 8);
                    bl2[j][0] = *(const uint32_t*)q;
                    bl2[j][1] = *(const uint32_t*)(q + 8);
                }
#pragma unroll
                for (int i = 0; i < 2; i++) {
                    const int ar = wm * 32 + i * 16 + gr;
                    const __nv_bfloat16* p = sQh + ar * 88 + kb;
                    const __nv_bfloat16* q = sQl + ar * 88 + kb;
                    uint32_t ah[4], al[4];
                    ah[0] = *(const uint32_t*)p;
                    ah[1] = *(const uint32_t*)(p + 8 * 88);
                    ah[2] = *(const uint32_t*)(p + 8);
                    ah[3] = *(const uint32_t*)(p + 8 * 88 + 8);
                    al[0] = *(const uint32_t*)q;
                    al[1] = *(const uint32_t*)(q + 8 * 88);
                    al[2] = *(const uint32_t*)(q + 8);
                    al[3] = *(const uint32_t*)(q + 8 * 88 + 8);
#pragma unroll
                    for (int j = 0; j < 2; j++) {
                        mma_bf16(sacc[i][j], ah, bh2[j]);
                        mma_bf16(sacc[i][j], ah, bl2[j]);
                        mma_bf16(sacc[i][j], al, bh2[j]);
                    }
                }
            }
#pragma unroll
            for (int i = 0; i < 2; i++)
#pragma unroll
                for (int j = 0; j < 2; j++) {
                    const int row = wm * 32 + i * 16 + gr;
                    const int col = wn * 16 + j * 8 + 2 * c4;
                    *(float2*)&sPs[row * 68 + col] =
                        make_float2(sacc[i][j][0], sacc[i][j][1]);
                    *(float2*)&sPs[(row + 8) * 68 + col] =
                        make_float2(sacc[i][j][2], sacc[i][j][3]);
                }
        }
        __syncthreads();

        // ---- softmax (row r_row, cols r_sub*16..+15), emit Ph/Pl bf16 ----
        {
            const float* prow = sPs + r_row * 68 + r_sub * 16;
            float4 t0 = *(const float4*)(prow + 0);
            float4 t1 = *(const float4*)(prow + 4);
            float4 t2 = *(const float4*)(prow + 8);
            float4 t3 = *(const float4*)(prow + 12);
            float tmax = fmaxf(fmaxf(fmaxf(t0.x,t0.y),fmaxf(t0.z,t0.w)),
                               fmaxf(fmaxf(t1.x,t1.y),fmaxf(t1.z,t1.w)));
            tmax = fmaxf(tmax, fmaxf(fmaxf(t2.x,t2.y),fmaxf(t2.z,t2.w)));
            tmax = fmaxf(tmax, fmaxf(fmaxf(t3.x,t3.y),fmaxf(t3.z,t3.w)));
            tmax = fmaxf(tmax, __shfl_xor_sync(0xffffffffu, tmax, 1));
            tmax = fmaxf(tmax, __shfl_xor_sync(0xffffffffu, tmax, 2));
            float nm = fmaxf(m_, tmax);
            float corr = __expf(m_ - nm);
            t0.x=__expf(t0.x-nm); t0.y=__expf(t0.y-nm); t0.z=__expf(t0.z-nm); t0.w=__expf(t0.w-nm);
            t1.x=__expf(t1.x-nm); t1.y=__expf(t1.y-nm); t1.z=__expf(t1.z-nm); t1.w=__expf(t1.w-nm);
            t2.x=__expf(t2.x-nm); t2.y=__expf(t2.y-nm); t2.z=__expf(t2.z-nm); t2.w=__expf(t2.w-nm);
            t3.x=__expf(t3.x-nm); t3.y=__expf(t3.y-nm); t3.z=__expf(t3.z-nm); t3.w=__expf(t3.w-nm);
            float ps = (t0.x+t0.y+t0.z+t0.w) + (t1.x+t1.y+t1.z+t1.w)
                     + (t2.x+t2.y+t2.z+t2.w) + (t3.x+t3.y+t3.z+t3.w);
            ps += __shfl_xor_sync(0xffffffffu, ps, 1);
            ps += __shfl_xor_sync(0xffffffffu, ps, 2);
            l_ = l_ * corr + ps;
            m_ = nm;

            __nv_bfloat16* ph = sPh + r_row * 72 + r_sub * 16;
            __nv_bfloat16* pl = sPl + r_row * 72 + r_sub * 16;
            uint32_t hh, ll;
            split2(t0.x, t0.y, hh, ll); *(uint32_t*)(ph+ 0)=hh; *(uint32_t*)(pl+ 0)=ll;
            split2(t0.z, t0.w, hh, ll); *(uint32_t*)(ph+ 2)=hh; *(uint32_t*)(pl+ 2)=ll;
            split2(t1.x, t1.y, hh, ll); *(uint32_t*)(ph+ 4)=hh; *(uint32_t*)(pl+ 4)=ll;
            split2(t1.z, t1.w, hh, ll); *(uint32_t*)(ph+ 6)=hh; *(uint32_t*)(pl+ 6)=ll;
            split2(t2.x, t2.y, hh, ll); *(uint32_t*)(ph+ 8)=hh; *(uint32_t*)(pl+ 8)=ll;
            split2(t2.z, t2.w, hh, ll); *(uint32_t*)(ph+10)=hh; *(uint32_t*)(pl+10)=ll;
            split2(t3.x, t3.y, hh, ll); *(uint32_t*)(ph+12)=hh; *(uint32_t*)(pl+12)=ll;
            split2(t3.z, t3.w, hh, ll); *(uint32_t*)(ph+14)=hh; *(uint32_t*)(pl+14)=ll;
            if (r_sub == 0) sRow[r_row] = corr;
        }
        __syncthreads();

        // ---- PV: O = corr*O + P V via MMA (3 terms) ----
        {
            const float cr0 = sRow[wm2 * 16 + gr];
            const float cr1 = sRow[wm2 * 16 + gr + 8];
#pragma unroll
            for (int j = 0; j < 5; j++) {
                oacc[j][0] *= cr0; oacc[j][1] *= cr0;
                oacc[j][2] *= cr1; oacc[j][3] *= cr1;
            }
#pragma unroll
            for (int ks = 0; ks < 4; ks++) {
                const __nv_bfloat16* p = sPh + (wm2 * 16 + gr) * 72 + ks * 16 + 2 * c4;
                const __nv_bfloat16* q = sPl + (wm2 * 16 + gr) * 72 + ks * 16 + 2 * c4;
                uint32_t ph[4], pl[4];
                ph[0] = *(const uint32_t*)p;
                ph[1] = *(const uint32_t*)(p + 8 * 72);
                ph[2] = *(const uint32_t*)(p + 8);
                ph[3] = *(const uint32_t*)(p + 8 * 72 + 8);
                pl[0] = *(const uint32_t*)q;
                pl[1] = *(const uint32_t*)(q + 8 * 72);
                pl[2] = *(const uint32_t*)(q + 8);
                pl[3] = *(const uint32_t*)(q + 8 * 72 + 8);
                const uint32_t rowb = vh_base +
                    (uint32_t)(((ks * 16 + (lane & 15)) * 88) * 2);
#pragma unroll
                for (int j = 0; j < 5; j++) {
                    const uint32_t va = rowb + (uint32_t)((wn2 * 40 + j * 8) * 2);
                    uint32_t vh2[2], vl2[2];
                    ldsm_x2_trans(vh2[0], vh2[1], va);
                    ldsm_x2_trans(vl2[0], vl2[1], va + 11264u);
                    mma_bf16(oacc[j], ph, vh2);
                    mma_bf16(oacc[j], ph, vl2);
                    mma_bf16(oacc[j], pl, vh2);
                }
            }
        }

        // ---- pass epilogues at t==15 (own) and t==31 (encoder) ----
        if (t == 15 || t == 31) {
            __syncthreads();
            if (r_sub == 0) sRow[r_row] = 1.0f / l_;
            __syncthreads();
            const float i0 = sRow[wm2 * 16 + gr];
            const float i1 = sRow[wm2 * 16 + gr + 8];
            if (t == 15) {
                const int q0 = n0 + wm2 * 16 + gr;
                uint32_t* dh = (uint32_t*)g_oh;
                uint32_t* dl = (uint32_t*)g_ol;
#pragma unroll
                for (int j = 0; j < 5; j++) {
                    const int dim = wn2 * 40 + j * 8 + 2 * c4;
                    xo[j*4+0] = oacc[j][0] * i0; xo[j*4+1] = oacc[j][1] * i0;
                    xo[j*4+2] = oacc[j][2] * i1; xo[j*4+3] = oacc[j][3] * i1;
                    if (dim < 72) {
                        const size_t i0x = (((size_t)(b * SEQ + q0)) * DIM
                                            + h * HDIM + dim) >> 1;
                        const size_t i1x = (((size_t)(b * SEQ + q0 + 8)) * DIM
                                            + h * HDIM + dim) >> 1;
                        uint32_t hh, ll;
                        split2(xo[j*4+0], xo[j*4+1], hh, ll);
                        dh[i0x] = hh; dl[i0x] = ll;
                        split2(xo[j*4+2], xo[j*4+3], hh, ll);
                        dh[i1x] = hh; dl[i1x] = ll;
                    }
                }
                // reset online softmax + accumulators for pass 1
                m_ = -1e30f; l_ = 0.f;
#pragma unroll
                for (int j = 0; j < 5; j++)
#pragma unroll
                    for (int r = 0; r < 4; r++) oacc[j][r] = 0.f;
            } else {
#pragma unroll
                for (int j = 0; j < 5; j++) {
                    const int dim = wn2 * 40 + j * 8 + 2 * c4;
                    if (dim < 72) {
                        float e0 = xo[j*4+0] - oacc[j][0] * i0;
                        float e1 = xo[j*4+1] - oacc[j][1] * i0;
                        float e2 = xo[j*4+2] - oacc[j][2] * i1;
                        float e3 = xo[j*4+3] - oacc[j][3] * i1;
                        lsum += e0*e0 + e1*e1 + e2*e2 + e3*e3;
                    }
                }
            }
        }
    }

    // loss reduction
    lsum *= (1.0f / TOTAL_ELEMS);
#pragma unroll
    for (int o = 16; o > 0; o >>= 1)
        lsum += __shfl_down_sync(0xffffffffu, lsum, o);
    if (lane == 0) atomicAdd(loss_out, lsum);
}

// ---------------------------------------------------------------------------
extern "C" void kernel_launch(void* const* d_in, const int* in_sizes, int n_in,
                              void* d_out, int out_size)
{
    const float* x      = (const float*)d_in[0];
    const float* enc_k  = (const float*)d_in[1];
    const float* enc_v  = (const float*)d_in[2];
    const float* qkv_w  = (const float*)d_in[3];
    const float* qkv_b  = (const float*)d_in[4];
    const float* proj_w = (const float*)d_in[5];
    const float* proj_b = (const float*)d_in[6];
    float* out = (float*)d_out;
    float* loss_ptr = out + (out_size - 1);

    __nv_bfloat16 *xh, *xl, *wqh, *wql, *wph, *wpl, *oh, *ol;
    __nv_bfloat16 *ekh, *ekl, *evh, *evl;
    cudaGetSymbolAddress((void**)&xh,  g_xh);   cudaGetSymbolAddress((void**)&xl,  g_xl);
    cudaGetSymbolAddress((void**)&wqh, g_wqh);  cudaGetSymbolAddress((void**)&wql, g_wql);
    cudaGetSymbolAddress((void**)&wph, g_wph);  cudaGetSymbolAddress((void**)&wpl, g_wpl);
    cudaGetSymbolAddress((void**)&oh,  g_oh);   cudaGetSymbolAddress((void**)&ol,  g_ol);
    cudaGetSymbolAddress((void**)&ekh, g_ekh);  cudaGetSymbolAddress((void**)&ekl, g_ekl);
    cudaGetSymbolAddress((void**)&evh, g_evh);  cudaGetSymbolAddress((void**)&evl, g_evl);

    static bool attr_set = false;
    if (!attr_set) {
        cudaFuncSetAttribute(attn_kernel,
                             cudaFuncAttributeMaxDynamicSharedMemorySize, AT_SMEM_BYTES);
        cudaFuncSetAttribute(gemm_mma_kernel<0>,
                             cudaFuncAttributeMaxDynamicSharedMemorySize, GM_SMEM_BYTES);
        cudaFuncSetAttribute(gemm_mma_kernel<1>,
                             cudaFuncAttributeMaxDynamicSharedMemorySize, GM_SMEM_BYTES);
        attr_set = true;
    }

    cudaMemsetAsync(loss_ptr, 0, sizeof(float));

    // 0) fp32 -> bf16 hi/lo splits (GEMM inputs + encoder K/V)
    {
        int n4x = (ROWS * DIM) / 4;
        int n4q = (QKVN * DIM) / 4;
        int n4p = (DIM * DIM) / 4;
        split_bf16_kernel<<<(n4x + 255) / 256, 256>>>(x,      xh,  xl,  n4x);
        split_bf16_kernel<<<(n4q + 255) / 256, 256>>>(qkv_w,  wqh, wql, n4q);
        split_bf16_kernel<<<(n4p + 255) / 256, 256>>>(proj_w, wph, wpl, n4p);
        split_bf16_kernel<<<(n4x + 255) / 256, 256>>>(enc_k,  ekh, ekl, n4x);
        split_bf16_kernel<<<(n4x + 255) / 256, 256>>>(enc_v,  evh, evl, n4x);
    }

    // 1) QKV GEMM (tensor cores) -> head-major bf16 hi/lo Q(scaled)/K/V
    gemm_mma_kernel<1><<<dim3(QKVN / 128, ROWS / 128), 256, GM_SMEM_BYTES>>>(
        xh, xl, wqh, wql, qkv_b, nullptr, ROWS, QKVN, DIM);

    // 2) Dual attention + loss (tensor cores) -> g_oh/g_ol + loss scalar
    attn_kernel<<<dim3(SEQ / 64, BATCH * HEADS), 256, AT_SMEM_BYTES>>>(loss_ptr);

    // 3) proj GEMM (tensor cores) -> out
    gemm_mma_kernel<0><<<dim3(DIM / 128, ROWS / 128), 256, GM_SMEM_BYTES>>>(
        oh, ol, wph, wpl, proj_b, out, ROWS, DIM, DIM);
}